// round 1
// baseline (speedup 1.0000x reference)
#include <cuda_runtime.h>
#include <math.h>

#define B_ 8
#define N_ 5
#define C_ 256
#define HW_ 4096
#define M_ 32768   // B*HW

// ---------------- scratch (static device globals; no runtime allocation) ----
__device__ float g_sum  [B_*C_*HW_];     // sum over all 5 frames
__device__ float g_proj [B_*N_*4*HW_];   // proj[b,j,p,hw]
__device__ float g_mt   [B_*C_*HW_];     // m_t for current i
__device__ float g_u    [B_*C_*HW_];     // sigmoid(u_pre)
__device__ float g_rh   [B_*C_*HW_];     // h_t * sigmoid(r_pre)
__device__ float g_opart[B_*C_*HW_];     // W_o_left @ m_t + b_o
__device__ float g_Wcat [768*512];       // [w_u; w_r; w_o_left|0]
__device__ float g_bcat [768];

// ---------------- prep: build concatenated weight matrix ---------------------
__global__ void prep_kernel(const float* __restrict__ wu, const float* __restrict__ wr,
                            const float* __restrict__ wo, const float* __restrict__ bu,
                            const float* __restrict__ br, const float* __restrict__ bo) {
    int idx = blockIdx.x * 256 + threadIdx.x;
    if (idx < 768 * 512) {
        int o = idx >> 9, k = idx & 511;
        float v;
        if (o < 256)       v = wu[o * 512 + k];
        else if (o < 512)  v = wr[(o - 256) * 512 + k];
        else               v = (k < 256) ? wo[(o - 512) * 512 + k] : 0.f;
        g_Wcat[idx] = v;
    }
    if (idx < 768) {
        g_bcat[idx] = (idx < 256) ? bu[idx] : (idx < 512 ? br[idx - 256] : bo[idx - 512]);
    }
}

// ---------------- sum over frames + 20 gate projections per pixel ------------
__global__ void sumproj_kernel(const float* __restrict__ inp, const float* __restrict__ wgt_w) {
    __shared__ float wsm[4 * 256];             // wgt_w[p][c]
    int tid = threadIdx.x;
    for (int t = tid; t < 1024; t += 256) wsm[t] = wgt_w[t];
    __syncthreads();

    int m  = blockIdx.x * 256 + tid;           // pixel id
    int b  = m >> 12;
    int hw = m & 4095;

    float pj[N_][4];
#pragma unroll
    for (int j = 0; j < N_; j++)
#pragma unroll
        for (int p = 0; p < 4; p++) pj[j][p] = 0.f;

    const float* base = inp + (size_t)b * N_ * C_ * HW_ + hw;
    for (int c = 0; c < C_; c++) {
        float w0 = wsm[c], w1 = wsm[256 + c], w2 = wsm[512 + c], w3 = wsm[768 + c];
        float s = 0.f;
#pragma unroll
        for (int j = 0; j < N_; j++) {
            float v = base[(j * C_ + c) * HW_];
            s += v;
            pj[j][0] += v * w0; pj[j][1] += v * w1;
            pj[j][2] += v * w2; pj[j][3] += v * w3;
        }
        g_sum[((b << 8) + c) * HW_ + hw] = s;
    }
#pragma unroll
    for (int j = 0; j < N_; j++)
#pragma unroll
        for (int p = 0; p < 4; p++)
            g_proj[(((b * N_ + j) << 2) + p) * HW_ + hw] = pj[j][p];
}

// ---------------- m_t = sigmoid(wgt[c%4]) * (sum_all - h_t) ------------------
__global__ void mt_kernel(const float* __restrict__ inp, int i) {
    int idx = blockIdx.x * 256 + threadIdx.x;  // over B*C*HW
    int hw = idx & 4095;
    int c  = (idx >> 12) & 255;
    int b  = idx >> 20;
    int p  = c & 3;
    int jp = (p < i) ? p : p + 1;              // idx[p] for this i
    float a0 = g_proj[(((b * N_ + i)  << 2) + p) * HW_ + hw];
    float a1 = g_proj[(((b * N_ + jp) << 2) + p) * HW_ + hw];
    float gate = 1.f / (1.f + expf(-(a0 - a1)));
    float ht = inp[(((size_t)(b * N_ + i) << 8) + c) * HW_ + hw];
    g_mt[idx] = gate * (g_sum[idx] - ht);
}

// ---------------- GEMM1: [u_pre; r_pre; opart] = Wcat @ [m_t; h_t] -----------
// 128x128 block tile, BK=8, 256 threads, 8x8 per thread.
// tx indexes M (pixels, contiguous hw -> coalesced epilogue), ty indexes N.
__global__ __launch_bounds__(256, 2)
void gemm1_kernel(const float* __restrict__ inp, int i) {
    __shared__ float As[8][128];
    __shared__ float Ws[8][132];
    const int tid   = threadIdx.x;
    const int nBase = blockIdx.x * 128;
    const int mBase = blockIdx.y * 128;
    const int tx = tid & 15;        // m
    const int ty = tid >> 4;        // n
    const int b  = mBase >> 12;

    const int ak  = tid >> 5;               // k row 0..7
    const int am  = (tid & 31) << 2;        // m offset 0..124
    const int hwA = (mBase + am) & 4095;

    const int wn = tid >> 1;                // n row 0..127
    const int wk = (tid & 1) << 2;          // k offset 0 or 4
    const float* wptr = g_Wcat + (size_t)(nBase + wn) * 512 + wk;

    const float* htbase = inp + (size_t)(b * N_ + i) * C_ * HW_;

    float acc[8][8];
#pragma unroll
    for (int x = 0; x < 8; x++)
#pragma unroll
        for (int y = 0; y < 8; y++) acc[x][y] = 0.f;

    for (int kb = 0; kb < 512; kb += 8) {
        int k = kb + ak;
        const float* ap = (k < 256)
            ? (g_mt + (size_t)((b << 8) + k) * HW_ + hwA)
            : (htbase + (size_t)(k - 256) * HW_ + hwA);
        float4 av = *(const float4*)ap;
        float4 wv = *(const float4*)(wptr + kb);
        __syncthreads();
        *(float4*)&As[ak][am] = av;
        Ws[wk + 0][wn] = wv.x; Ws[wk + 1][wn] = wv.y;
        Ws[wk + 2][wn] = wv.z; Ws[wk + 3][wn] = wv.w;
        __syncthreads();
#pragma unroll
        for (int kk = 0; kk < 8; kk++) {
            float4 a0 = *(const float4*)&As[kk][tx * 8];
            float4 a1 = *(const float4*)&As[kk][tx * 8 + 4];
            float4 w0 = *(const float4*)&Ws[kk][ty * 8];
            float4 w1 = *(const float4*)&Ws[kk][ty * 8 + 4];
            float ar[8] = {a0.x, a0.y, a0.z, a0.w, a1.x, a1.y, a1.z, a1.w};
            float wr8[8] = {w0.x, w0.y, w0.z, w0.w, w1.x, w1.y, w1.z, w1.w};
#pragma unroll
            for (int x = 0; x < 8; x++)
#pragma unroll
                for (int y = 0; y < 8; y++)
                    acc[x][y] += ar[x] * wr8[y];
        }
    }

    const int hwE = (mBase + tx * 8) & 4095;
    const int seg = nBase >> 8;   // 0=u, 1=r, 2=opart (block fully inside one segment)
#pragma unroll
    for (int ny = 0; ny < 8; ny++) {
        int o = nBase + ty * 8 + ny;
        float bias = g_bcat[o];
        float v[8];
#pragma unroll
        for (int x = 0; x < 8; x++) v[x] = acc[x][ny] + bias;
        if (seg == 0) {
#pragma unroll
            for (int x = 0; x < 8; x++) v[x] = 1.f / (1.f + expf(-v[x]));
            float* dst = g_u + (size_t)((b << 8) + o) * HW_ + hwE;
            *(float4*)dst       = make_float4(v[0], v[1], v[2], v[3]);
            *(float4*)(dst + 4) = make_float4(v[4], v[5], v[6], v[7]);
        } else if (seg == 1) {
            int c = o - 256;
            const float* hp = htbase + (size_t)c * HW_ + hwE;
            float4 h0 = *(const float4*)hp, h1 = *(const float4*)(hp + 4);
            float hv[8] = {h0.x, h0.y, h0.z, h0.w, h1.x, h1.y, h1.z, h1.w};
#pragma unroll
            for (int x = 0; x < 8; x++) v[x] = hv[x] / (1.f + expf(-v[x]));
            float* dst = g_rh + (size_t)((b << 8) + c) * HW_ + hwE;
            *(float4*)dst       = make_float4(v[0], v[1], v[2], v[3]);
            *(float4*)(dst + 4) = make_float4(v[4], v[5], v[6], v[7]);
        } else {
            float* dst = g_opart + (size_t)((b << 8) + (o - 512)) * HW_ + hwE;
            *(float4*)dst       = make_float4(v[0], v[1], v[2], v[3]);
            *(float4*)(dst + 4) = make_float4(v[4], v[5], v[6], v[7]);
        }
    }
}

// ---------------- GEMM2: o_pre = opart + W_o_right @ rh; final combine -------
__global__ __launch_bounds__(256, 2)
void gemm2_kernel(const float* __restrict__ inp, const float* __restrict__ wo,
                  const float* __restrict__ gamma, float* __restrict__ out, int i) {
    __shared__ float As[8][128];
    __shared__ float Ws[8][132];
    const int tid   = threadIdx.x;
    const int nBase = blockIdx.x * 128;
    const int mBase = blockIdx.y * 128;
    const int tx = tid & 15;
    const int ty = tid >> 4;
    const int b  = mBase >> 12;

    const int ak  = tid >> 5;
    const int am  = (tid & 31) << 2;
    const int hwA = (mBase + am) & 4095;

    const int wn = tid >> 1;
    const int wk = (tid & 1) << 2;
    const float* wptr = wo + (size_t)(nBase + wn) * 512 + 256 + wk;  // right half of w_o

    const float* htbase = inp + (size_t)(b * N_ + i) * C_ * HW_;

    float acc[8][8];
#pragma unroll
    for (int x = 0; x < 8; x++)
#pragma unroll
        for (int y = 0; y < 8; y++) acc[x][y] = 0.f;

    for (int kb = 0; kb < 256; kb += 8) {
        int k = kb + ak;
        const float* ap = g_rh + (size_t)((b << 8) + k) * HW_ + hwA;
        float4 av = *(const float4*)ap;
        float4 wv = *(const float4*)(wptr + kb);
        __syncthreads();
        *(float4*)&As[ak][am] = av;
        Ws[wk + 0][wn] = wv.x; Ws[wk + 1][wn] = wv.y;
        Ws[wk + 2][wn] = wv.z; Ws[wk + 3][wn] = wv.w;
        __syncthreads();
#pragma unroll
        for (int kk = 0; kk < 8; kk++) {
            float4 a0 = *(const float4*)&As[kk][tx * 8];
            float4 a1 = *(const float4*)&As[kk][tx * 8 + 4];
            float4 w0 = *(const float4*)&Ws[kk][ty * 8];
            float4 w1 = *(const float4*)&Ws[kk][ty * 8 + 4];
            float ar[8] = {a0.x, a0.y, a0.z, a0.w, a1.x, a1.y, a1.z, a1.w};
            float wr8[8] = {w0.x, w0.y, w0.z, w0.w, w1.x, w1.y, w1.z, w1.w};
#pragma unroll
            for (int x = 0; x < 8; x++)
#pragma unroll
                for (int y = 0; y < 8; y++)
                    acc[x][y] += ar[x] * wr8[y];
        }
    }

    const int hwE = (mBase + tx * 8) & 4095;
    const float gm = gamma[0];
#pragma unroll
    for (int ny = 0; ny < 8; ny++) {
        int o = nBase + ty * 8 + ny;
        const float* opp = g_opart + (size_t)((b << 8) + o) * HW_ + hwE;
        const float* up  = g_u     + (size_t)((b << 8) + o) * HW_ + hwE;
        const float* hp  = htbase  + (size_t)o * HW_ + hwE;
        float4 op0 = *(const float4*)opp, op1 = *(const float4*)(opp + 4);
        float4 u0  = *(const float4*)up,  u1  = *(const float4*)(up + 4);
        float4 h0  = *(const float4*)hp,  h1  = *(const float4*)(hp + 4);
        float opv[8] = {op0.x, op0.y, op0.z, op0.w, op1.x, op1.y, op1.z, op1.w};
        float uv[8]  = {u0.x,  u0.y,  u0.z,  u0.w,  u1.x,  u1.y,  u1.z,  u1.w};
        float hv[8]  = {h0.x,  h0.y,  h0.z,  h0.w,  h1.x,  h1.y,  h1.z,  h1.w};
        float v[8];
#pragma unroll
        for (int x = 0; x < 8; x++) {
            float opre = acc[x][ny] + opv[x];
            float u = uv[x], ht = hv[x];
            float hn = ht * (1.f - u) + tanhf(opre) * u;
            v[x] = hn * gm + ht;
        }
        float* dst = out + ((size_t)(b * N_ + i) * C_ + o) * HW_ + hwE;
        *(float4*)dst       = make_float4(v[0], v[1], v[2], v[3]);
        *(float4*)(dst + 4) = make_float4(v[4], v[5], v[6], v[7]);
    }
}

// ---------------- launch ----------------------------------------------------
extern "C" void kernel_launch(void* const* d_in, const int* in_sizes, int n_in,
                              void* d_out, int out_size) {
    const float* inp   = (const float*)d_in[0];
    const float* wgt_w = (const float*)d_in[1];
    const float* w_r   = (const float*)d_in[2];
    const float* b_r   = (const float*)d_in[3];
    const float* w_u   = (const float*)d_in[4];
    const float* b_u   = (const float*)d_in[5];
    const float* w_o   = (const float*)d_in[6];
    const float* b_o   = (const float*)d_in[7];
    const float* gamma = (const float*)d_in[8];
    float* out = (float*)d_out;

    prep_kernel<<<(768 * 512 + 255) / 256, 256>>>(w_u, w_r, w_o, b_u, b_r, b_o);
    sumproj_kernel<<<M_ / 256, 256>>>(inp, wgt_w);

    for (int i = 0; i < N_; i++) {
        mt_kernel<<<(B_ * C_ * HW_) / 256, 256>>>(inp, i);
        gemm1_kernel<<<dim3(6, 256), 256>>>(inp, i);
        gemm2_kernel<<<dim3(2, 256), 256>>>(inp, w_o, gamma, out, i);
    }
}

// round 2
// speedup vs baseline: 1.0016x; 1.0016x over previous
#include <cuda_runtime.h>
#include <math.h>

#define B_ 8
#define N_ 5
#define C_ 256
#define HW_ 4096
#define M_ 32768   // B*HW

// ---------------- scratch (static device globals; no runtime allocation) ----
__device__ float g_sum  [B_*C_*HW_];     // sum over all 5 frames
__device__ float g_proj [B_*N_*4*HW_];   // proj[b,j,p,hw]
__device__ float g_mt   [B_*C_*HW_];     // m_t for current i
__device__ float g_u    [B_*C_*HW_];     // sigmoid(u_pre)
__device__ float g_rh   [B_*C_*HW_];     // h_t * sigmoid(r_pre)
__device__ float g_opart[B_*C_*HW_];     // W_o_left @ m_t + b_o
__device__ float g_Wcat [768*512];       // [w_u; w_r; w_o_left|0]
__device__ float g_bcat [768];

// ---------------- prep: build concatenated weight matrix ---------------------
__global__ void prep_kernel(const float* __restrict__ wu, const float* __restrict__ wr,
                            const float* __restrict__ wo, const float* __restrict__ bu,
                            const float* __restrict__ br, const float* __restrict__ bo) {
    int idx = blockIdx.x * 256 + threadIdx.x;
    if (idx < 768 * 512) {
        int o = idx >> 9, k = idx & 511;
        float v;
        if (o < 256)       v = wu[o * 512 + k];
        else if (o < 512)  v = wr[(o - 256) * 512 + k];
        else               v = (k < 256) ? wo[(o - 512) * 512 + k] : 0.f;
        g_Wcat[idx] = v;
    }
    if (idx < 768) {
        g_bcat[idx] = (idx < 256) ? bu[idx] : (idx < 512 ? br[idx - 256] : bo[idx - 512]);
    }
}

// ---------------- sum over frames + 20 gate projections per pixel ------------
__global__ void sumproj_kernel(const float* __restrict__ inp, const float* __restrict__ wgt_w) {
    __shared__ float wsm[4 * 256];             // wgt_w[p][c]
    int tid = threadIdx.x;
    for (int t = tid; t < 1024; t += 256) wsm[t] = wgt_w[t];
    __syncthreads();

    int m  = blockIdx.x * 256 + tid;           // pixel id
    int b  = m >> 12;
    int hw = m & 4095;

    float pj[N_][4];
#pragma unroll
    for (int j = 0; j < N_; j++)
#pragma unroll
        for (int p = 0; p < 4; p++) pj[j][p] = 0.f;

    const float* base = inp + (size_t)b * N_ * C_ * HW_ + hw;
    for (int c = 0; c < C_; c++) {
        float w0 = wsm[c], w1 = wsm[256 + c], w2 = wsm[512 + c], w3 = wsm[768 + c];
        float s = 0.f;
#pragma unroll
        for (int j = 0; j < N_; j++) {
            float v = base[(j * C_ + c) * HW_];
            s += v;
            pj[j][0] += v * w0; pj[j][1] += v * w1;
            pj[j][2] += v * w2; pj[j][3] += v * w3;
        }
        g_sum[((b << 8) + c) * HW_ + hw] = s;
    }
#pragma unroll
    for (int j = 0; j < N_; j++)
#pragma unroll
        for (int p = 0; p < 4; p++)
            g_proj[(((b * N_ + j) << 2) + p) * HW_ + hw] = pj[j][p];
}

// ---------------- m_t = sigmoid(wgt[c%4]) * (sum_all - h_t) ------------------
__global__ void mt_kernel(const float* __restrict__ inp, int i) {
    int idx = blockIdx.x * 256 + threadIdx.x;  // over B*C*HW
    int hw = idx & 4095;
    int c  = (idx >> 12) & 255;
    int b  = idx >> 20;
    int p  = c & 3;
    int jp = (p < i) ? p : p + 1;              // idx[p] for this i
    float a0 = g_proj[(((b * N_ + i)  << 2) + p) * HW_ + hw];
    float a1 = g_proj[(((b * N_ + jp) << 2) + p) * HW_ + hw];
    float gate = 1.f / (1.f + expf(-(a0 - a1)));
    float ht = inp[(((size_t)(b * N_ + i) << 8) + c) * HW_ + hw];
    g_mt[idx] = gate * (g_sum[idx] - ht);
}

// ---------------- GEMM1: [u_pre; r_pre; opart] = Wcat @ [m_t; h_t] -----------
// 128x128 block tile, BK=8, 256 threads, 8x8 per thread.
// tx indexes M (pixels, contiguous hw -> coalesced epilogue), ty indexes N.
__global__ __launch_bounds__(256, 2)
void gemm1_kernel(const float* __restrict__ inp, int i) {
    __shared__ float As[8][128];
    __shared__ float Ws[8][132];
    const int tid   = threadIdx.x;
    const int nBase = blockIdx.x * 128;
    const int mBase = blockIdx.y * 128;
    const int tx = tid & 15;        // m
    const int ty = tid >> 4;        // n
    const int b  = mBase >> 12;

    const int ak  = tid >> 5;               // k row 0..7
    const int am  = (tid & 31) << 2;        // m offset 0..124
    const int hwA = (mBase + am) & 4095;

    const int wn = tid >> 1;                // n row 0..127
    const int wk = (tid & 1) << 2;          // k offset 0 or 4
    const float* wptr = g_Wcat + (size_t)(nBase + wn) * 512 + wk;

    const float* htbase = inp + (size_t)(b * N_ + i) * C_ * HW_;

    float acc[8][8];
#pragma unroll
    for (int x = 0; x < 8; x++)
#pragma unroll
        for (int y = 0; y < 8; y++) acc[x][y] = 0.f;

    for (int kb = 0; kb < 512; kb += 8) {
        int k = kb + ak;
        const float* ap = (k < 256)
            ? (g_mt + (size_t)((b << 8) + k) * HW_ + hwA)
            : (htbase + (size_t)(k - 256) * HW_ + hwA);
        float4 av = *(const float4*)ap;
        float4 wv = *(const float4*)(wptr + kb);
        __syncthreads();
        *(float4*)&As[ak][am] = av;
        Ws[wk + 0][wn] = wv.x; Ws[wk + 1][wn] = wv.y;
        Ws[wk + 2][wn] = wv.z; Ws[wk + 3][wn] = wv.w;
        __syncthreads();
#pragma unroll
        for (int kk = 0; kk < 8; kk++) {
            float4 a0 = *(const float4*)&As[kk][tx * 8];
            float4 a1 = *(const float4*)&As[kk][tx * 8 + 4];
            float4 w0 = *(const float4*)&Ws[kk][ty * 8];
            float4 w1 = *(const float4*)&Ws[kk][ty * 8 + 4];
            float ar[8] = {a0.x, a0.y, a0.z, a0.w, a1.x, a1.y, a1.z, a1.w};
            float wr8[8] = {w0.x, w0.y, w0.z, w0.w, w1.x, w1.y, w1.z, w1.w};
#pragma unroll
            for (int x = 0; x < 8; x++)
#pragma unroll
                for (int y = 0; y < 8; y++)
                    acc[x][y] += ar[x] * wr8[y];
        }
    }

    const int hwE = (mBase + tx * 8) & 4095;
    const int seg = nBase >> 8;   // 0=u, 1=r, 2=opart (block fully inside one segment)
#pragma unroll
    for (int ny = 0; ny < 8; ny++) {
        int o = nBase + ty * 8 + ny;
        float bias = g_bcat[o];
        float v[8];
#pragma unroll
        for (int x = 0; x < 8; x++) v[x] = acc[x][ny] + bias;
        if (seg == 0) {
#pragma unroll
            for (int x = 0; x < 8; x++) v[x] = 1.f / (1.f + expf(-v[x]));
            float* dst = g_u + (size_t)((b << 8) + o) * HW_ + hwE;
            *(float4*)dst       = make_float4(v[0], v[1], v[2], v[3]);
            *(float4*)(dst + 4) = make_float4(v[4], v[5], v[6], v[7]);
        } else if (seg == 1) {
            int c = o - 256;
            const float* hp = htbase + (size_t)c * HW_ + hwE;
            float4 h0 = *(const float4*)hp, h1 = *(const float4*)(hp + 4);
            float hv[8] = {h0.x, h0.y, h0.z, h0.w, h1.x, h1.y, h1.z, h1.w};
#pragma unroll
            for (int x = 0; x < 8; x++) v[x] = hv[x] / (1.f + expf(-v[x]));
            float* dst = g_rh + (size_t)((b << 8) + c) * HW_ + hwE;
            *(float4*)dst       = make_float4(v[0], v[1], v[2], v[3]);
            *(float4*)(dst + 4) = make_float4(v[4], v[5], v[6], v[7]);
        } else {
            float* dst = g_opart + (size_t)((b << 8) + (o - 512)) * HW_ + hwE;
            *(float4*)dst       = make_float4(v[0], v[1], v[2], v[3]);
            *(float4*)(dst + 4) = make_float4(v[4], v[5], v[6], v[7]);
        }
    }
}

// ---------------- GEMM2: o_pre = opart + W_o_right @ rh; final combine -------
__global__ __launch_bounds__(256, 2)
void gemm2_kernel(const float* __restrict__ inp, const float* __restrict__ wo,
                  const float* __restrict__ gamma, float* __restrict__ out, int i) {
    __shared__ float As[8][128];
    __shared__ float Ws[8][132];
    const int tid   = threadIdx.x;
    const int nBase = blockIdx.x * 128;
    const int mBase = blockIdx.y * 128;
    const int tx = tid & 15;
    const int ty = tid >> 4;
    const int b  = mBase >> 12;

    const int ak  = tid >> 5;
    const int am  = (tid & 31) << 2;
    const int hwA = (mBase + am) & 4095;

    const int wn = tid >> 1;
    const int wk = (tid & 1) << 2;
    const float* wptr = wo + (size_t)(nBase + wn) * 512 + 256 + wk;  // right half of w_o

    const float* htbase = inp + (size_t)(b * N_ + i) * C_ * HW_;

    float acc[8][8];
#pragma unroll
    for (int x = 0; x < 8; x++)
#pragma unroll
        for (int y = 0; y < 8; y++) acc[x][y] = 0.f;

    for (int kb = 0; kb < 256; kb += 8) {
        int k = kb + ak;
        const float* ap = g_rh + (size_t)((b << 8) + k) * HW_ + hwA;
        float4 av = *(const float4*)ap;
        float4 wv = *(const float4*)(wptr + kb);
        __syncthreads();
        *(float4*)&As[ak][am] = av;
        Ws[wk + 0][wn] = wv.x; Ws[wk + 1][wn] = wv.y;
        Ws[wk + 2][wn] = wv.z; Ws[wk + 3][wn] = wv.w;
        __syncthreads();
#pragma unroll
        for (int kk = 0; kk < 8; kk++) {
            float4 a0 = *(const float4*)&As[kk][tx * 8];
            float4 a1 = *(const float4*)&As[kk][tx * 8 + 4];
            float4 w0 = *(const float4*)&Ws[kk][ty * 8];
            float4 w1 = *(const float4*)&Ws[kk][ty * 8 + 4];
            float ar[8] = {a0.x, a0.y, a0.z, a0.w, a1.x, a1.y, a1.z, a1.w};
            float wr8[8] = {w0.x, w0.y, w0.z, w0.w, w1.x, w1.y, w1.z, w1.w};
#pragma unroll
            for (int x = 0; x < 8; x++)
#pragma unroll
                for (int y = 0; y < 8; y++)
                    acc[x][y] += ar[x] * wr8[y];
        }
    }

    const int hwE = (mBase + tx * 8) & 4095;
    const float gm = gamma[0];
#pragma unroll
    for (int ny = 0; ny < 8; ny++) {
        int o = nBase + ty * 8 + ny;
        const float* opp = g_opart + (size_t)((b << 8) + o) * HW_ + hwE;
        const float* up  = g_u     + (size_t)((b << 8) + o) * HW_ + hwE;
        const float* hp  = htbase  + (size_t)o * HW_ + hwE;
        float4 op0 = *(const float4*)opp, op1 = *(const float4*)(opp + 4);
        float4 u0  = *(const float4*)up,  u1  = *(const float4*)(up + 4);
        float4 h0  = *(const float4*)hp,  h1  = *(const float4*)(hp + 4);
        float opv[8] = {op0.x, op0.y, op0.z, op0.w, op1.x, op1.y, op1.z, op1.w};
        float uv[8]  = {u0.x,  u0.y,  u0.z,  u0.w,  u1.x,  u1.y,  u1.z,  u1.w};
        float hv[8]  = {h0.x,  h0.y,  h0.z,  h0.w,  h1.x,  h1.y,  h1.z,  h1.w};
        float v[8];
#pragma unroll
        for (int x = 0; x < 8; x++) {
            float opre = acc[x][ny] + opv[x];
            float u = uv[x], ht = hv[x];
            float hn = ht * (1.f - u) + tanhf(opre) * u;
            v[x] = hn * gm + ht;
        }
        float* dst = out + ((size_t)(b * N_ + i) * C_ + o) * HW_ + hwE;
        *(float4*)dst       = make_float4(v[0], v[1], v[2], v[3]);
        *(float4*)(dst + 4) = make_float4(v[4], v[5], v[6], v[7]);
    }
}

// ---------------- launch ----------------------------------------------------
extern "C" void kernel_launch(void* const* d_in, const int* in_sizes, int n_in,
                              void* d_out, int out_size) {
    const float* inp   = (const float*)d_in[0];
    const float* wgt_w = (const float*)d_in[1];
    const float* w_r   = (const float*)d_in[2];
    const float* b_r   = (const float*)d_in[3];
    const float* w_u   = (const float*)d_in[4];
    const float* b_u   = (const float*)d_in[5];
    const float* w_o   = (const float*)d_in[6];
    const float* b_o   = (const float*)d_in[7];
    const float* gamma = (const float*)d_in[8];
    float* out = (float*)d_out;

    prep_kernel<<<(768 * 512 + 255) / 256, 256>>>(w_u, w_r, w_o, b_u, b_r, b_o);
    sumproj_kernel<<<M_ / 256, 256>>>(inp, wgt_w);

    for (int i = 0; i < N_; i++) {
        mt_kernel<<<(B_ * C_ * HW_) / 256, 256>>>(inp, i);
        gemm1_kernel<<<dim3(6, 256), 256>>>(inp, i);
        gemm2_kernel<<<dim3(2, 256), 256>>>(inp, w_o, gamma, out, i);
    }
}

// round 3
// speedup vs baseline: 1.9860x; 1.9828x over previous
#include <cuda_runtime.h>
#include <math.h>

#define B_ 8
#define N_ 5
#define C_ 256
#define HW_ 4096
#define M_ 32768   // B*HW
#define SAS 136    // smem row stride (floats): (8*k + r) mod 32 distinct -> conflict-free frags

// ---------------- scratch (static device globals; no runtime allocation) ----
__device__ float g_sum  [B_*C_*HW_];
__device__ float g_proj [B_*N_*4*HW_];
__device__ float g_mt   [B_*C_*HW_];
__device__ float g_u    [B_*C_*HW_];
__device__ float g_rh   [B_*C_*HW_];
__device__ float g_opart[B_*C_*HW_];
__device__ float g_Wcat [768*512];
__device__ float g_bcat [768];

__device__ __forceinline__ float tf32r(float x) {
    float r; asm("cvt.rna.tf32.f32 %0, %1;" : "=f"(r) : "f"(x)); return r;
}
__device__ __forceinline__ void mma_tf32(float* d, const unsigned* a, const unsigned* b) {
    asm volatile("mma.sync.aligned.m16n8k8.row.col.f32.tf32.tf32.f32 "
        "{%0,%1,%2,%3},{%4,%5,%6,%7},{%8,%9},{%0,%1,%2,%3};"
        : "+f"(d[0]), "+f"(d[1]), "+f"(d[2]), "+f"(d[3])
        : "r"(a[0]), "r"(a[1]), "r"(a[2]), "r"(a[3]), "r"(b[0]), "r"(b[1]));
}

// ---------------- prep: build concatenated weight matrix ---------------------
__global__ void prep_kernel(const float* __restrict__ wu, const float* __restrict__ wr,
                            const float* __restrict__ wo, const float* __restrict__ bu,
                            const float* __restrict__ br, const float* __restrict__ bo) {
    int idx = blockIdx.x * 256 + threadIdx.x;
    if (idx < 768 * 512) {
        int o = idx >> 9, k = idx & 511;
        float v;
        if (o < 256)       v = wu[o * 512 + k];
        else if (o < 512)  v = wr[(o - 256) * 512 + k];
        else               v = (k < 256) ? wo[(o - 512) * 512 + k] : 0.f;
        g_Wcat[idx] = v;
    }
    if (idx < 768) {
        g_bcat[idx] = (idx < 256) ? bu[idx] : (idx < 512 ? br[idx - 256] : bo[idx - 512]);
    }
}

// ---------------- sum over frames + 20 gate projections per pixel ------------
__global__ void sumproj_kernel(const float* __restrict__ inp, const float* __restrict__ wgt_w) {
    __shared__ float wsm[4 * 256];
    int tid = threadIdx.x;
    for (int t = tid; t < 1024; t += 256) wsm[t] = wgt_w[t];
    __syncthreads();

    int m  = blockIdx.x * 256 + tid;
    int b  = m >> 12;
    int hw = m & 4095;

    float pj[N_][4];
#pragma unroll
    for (int j = 0; j < N_; j++)
#pragma unroll
        for (int p = 0; p < 4; p++) pj[j][p] = 0.f;

    const float* base = inp + (size_t)b * N_ * C_ * HW_ + hw;
    for (int c = 0; c < C_; c++) {
        float w0 = wsm[c], w1 = wsm[256 + c], w2 = wsm[512 + c], w3 = wsm[768 + c];
        float s = 0.f;
#pragma unroll
        for (int j = 0; j < N_; j++) {
            float v = base[(j * C_ + c) * HW_];
            s += v;
            pj[j][0] += v * w0; pj[j][1] += v * w1;
            pj[j][2] += v * w2; pj[j][3] += v * w3;
        }
        g_sum[((b << 8) + c) * HW_ + hw] = s;
    }
#pragma unroll
    for (int j = 0; j < N_; j++)
#pragma unroll
        for (int p = 0; p < 4; p++)
            g_proj[(((b * N_ + j) << 2) + p) * HW_ + hw] = pj[j][p];
}

// ---------------- m_t = sigmoid(wgt[c%4]) * (sum_all - h_t) ------------------
__global__ void mt_kernel(const float* __restrict__ inp, int i) {
    int idx = blockIdx.x * 256 + threadIdx.x;
    int hw = idx & 4095;
    int c  = (idx >> 12) & 255;
    int b  = idx >> 20;
    int p  = c & 3;
    int jp = (p < i) ? p : p + 1;
    float a0 = g_proj[(((b * N_ + i)  << 2) + p) * HW_ + hw];
    float a1 = g_proj[(((b * N_ + jp) << 2) + p) * HW_ + hw];
    float gate = 1.f / (1.f + expf(-(a0 - a1)));
    float ht = inp[(((size_t)(b * N_ + i) << 8) + c) * HW_ + hw];
    g_mt[idx] = gate * (g_sum[idx] - ht);
}

// ---------------- GEMM1 (tf32 tensor): [u;r;opart] = Wcat @ [m_t; h_t] -------
// out tile: 128 pixels (M) x 128 chans (N), K=512, BK=16 double-buffered.
// 8 warps: 2(m) x 4(n); warp tile 64x32; 4x4 m16n8k8 fragments.
__global__ __launch_bounds__(256, 2)
void gemm1_kernel(const float* __restrict__ inp, int i) {
    __shared__ float As[2][16 * SAS];
    __shared__ float Ws[2][16 * SAS];
    const int tid   = threadIdx.x;
    const int nBase = blockIdx.x * 128;
    const int mBase = blockIdx.y * 128;
    const int b     = mBase >> 12;
    const int hwB   = mBase & 4095;
    const int lane  = tid & 31, wid = tid >> 5;
    const int wm = wid >> 2, wn = wid & 3;
    const int r_ = lane >> 2, c_ = lane & 3;

    const float* htbase = inp + (size_t)(b * N_ + i) * C_ * HW_;

    // staging: A (16k x 128px): thread loads rows krow, krow+8, float4 at grp*4
    const int krow = tid >> 5;
    const int grp  = tid & 31;
    const int hwA  = hwB + grp * 4;
    // staging: W: thread owns chan (tid>>1), half f
    const int wchL = tid >> 1;
    const int wf   = (tid & 1) * 4;
    const float* wbase = g_Wcat + (size_t)(nBase + wchL) * 512;

    float4 aR[2], wR[2];

    float acc[4][4][4];
#pragma unroll
    for (int mt = 0; mt < 4; mt++)
#pragma unroll
        for (int nt = 0; nt < 4; nt++)
#pragma unroll
            for (int q = 0; q < 4; q++) acc[mt][nt][q] = 0.f;

    const int NK = 512 / 16;

    // prologue
#pragma unroll
    for (int j = 0; j < 2; j++) {
        int kg = krow + j * 8;
        const float* ap = (kg < 256)
            ? (g_mt + (size_t)((b << 8) + kg) * HW_ + hwA)
            : (htbase + (size_t)(kg - 256) * HW_ + hwA);
        aR[j] = *(const float4*)ap;
        wR[j] = *(const float4*)(wbase + wf + j * 8);
    }
#pragma unroll
    for (int j = 0; j < 2; j++) {
        float* d = &As[0][(krow + j * 8) * SAS + grp * 4];
        d[0] = tf32r(aR[j].x); d[1] = tf32r(aR[j].y); d[2] = tf32r(aR[j].z); d[3] = tf32r(aR[j].w);
        int kb0 = wf + j * 8;
        Ws[0][(kb0 + 0) * SAS + wchL] = tf32r(wR[j].x);
        Ws[0][(kb0 + 1) * SAS + wchL] = tf32r(wR[j].y);
        Ws[0][(kb0 + 2) * SAS + wchL] = tf32r(wR[j].z);
        Ws[0][(kb0 + 3) * SAS + wchL] = tf32r(wR[j].w);
    }
    __syncthreads();

    for (int t = 0; t < NK; t++) {
        const int buf = t & 1;
        if (t + 1 < NK) {
            int kb = (t + 1) * 16;
#pragma unroll
            for (int j = 0; j < 2; j++) {
                int kg = kb + krow + j * 8;
                const float* ap = (kg < 256)
                    ? (g_mt + (size_t)((b << 8) + kg) * HW_ + hwA)
                    : (htbase + (size_t)(kg - 256) * HW_ + hwA);
                aR[j] = *(const float4*)ap;
                wR[j] = *(const float4*)(wbase + kb + wf + j * 8);
            }
        }
#pragma unroll
        for (int kk = 0; kk < 2; kk++) {
            unsigned af[4][4], bf[4][2];
#pragma unroll
            for (int mt = 0; mt < 4; mt++) {
                const float* p = &As[buf][(kk * 8 + c_) * SAS + wm * 64 + mt * 16 + r_];
                af[mt][0] = __float_as_uint(p[0]);
                af[mt][1] = __float_as_uint(p[8]);
                af[mt][2] = __float_as_uint(p[4 * SAS]);
                af[mt][3] = __float_as_uint(p[4 * SAS + 8]);
            }
#pragma unroll
            for (int nt = 0; nt < 4; nt++) {
                const float* p = &Ws[buf][(kk * 8 + c_) * SAS + wn * 32 + nt * 8 + r_];
                bf[nt][0] = __float_as_uint(p[0]);
                bf[nt][1] = __float_as_uint(p[4 * SAS]);
            }
#pragma unroll
            for (int mt = 0; mt < 4; mt++)
#pragma unroll
                for (int nt = 0; nt < 4; nt++)
                    mma_tf32(acc[mt][nt], af[mt], bf[nt]);
        }
        if (t + 1 < NK) {
            const int nb = buf ^ 1;
#pragma unroll
            for (int j = 0; j < 2; j++) {
                float* d = &As[nb][(krow + j * 8) * SAS + grp * 4];
                d[0] = tf32r(aR[j].x); d[1] = tf32r(aR[j].y); d[2] = tf32r(aR[j].z); d[3] = tf32r(aR[j].w);
                int kb0 = wf + j * 8;
                Ws[nb][(kb0 + 0) * SAS + wchL] = tf32r(wR[j].x);
                Ws[nb][(kb0 + 1) * SAS + wchL] = tf32r(wR[j].y);
                Ws[nb][(kb0 + 2) * SAS + wchL] = tf32r(wR[j].z);
                Ws[nb][(kb0 + 3) * SAS + wchL] = tf32r(wR[j].w);
            }
            __syncthreads();
        }
    }

    // epilogue: fragment (q): pixel = px0 + (q>>1)*8, chan = ch0 + (q&1)
    const int seg = nBase >> 8;  // 0=u, 1=r, 2=opart
#pragma unroll
    for (int mt = 0; mt < 4; mt++)
#pragma unroll
        for (int nt = 0; nt < 4; nt++) {
            int px0 = hwB + wm * 64 + mt * 16 + r_;
            int ch0 = nBase + wn * 32 + nt * 8 + c_ * 2;
#pragma unroll
            for (int q = 0; q < 4; q++) {
                int o  = ch0 + (q & 1);
                int hw = px0 + ((q >> 1) * 8);
                float v = acc[mt][nt][q] + g_bcat[o];
                if (seg == 0) {
                    g_u[(size_t)((b << 8) + o) * HW_ + hw] = 1.f / (1.f + expf(-v));
                } else if (seg == 1) {
                    int c = o - 256;
                    float ht = htbase[(size_t)c * HW_ + hw];
                    g_rh[(size_t)((b << 8) + c) * HW_ + hw] = ht / (1.f + expf(-v));
                } else {
                    g_opart[(size_t)((b << 8) + o - 512) * HW_ + hw] = v;
                }
            }
        }
}

// ---------------- GEMM2 (tf32 tensor): o_pre = opart + W_o_right @ rh --------
__global__ __launch_bounds__(256, 2)
void gemm2_kernel(const float* __restrict__ inp, const float* __restrict__ wo,
                  const float* __restrict__ gamma, float* __restrict__ out, int i) {
    __shared__ float As[2][16 * SAS];
    __shared__ float Ws[2][16 * SAS];
    const int tid   = threadIdx.x;
    const int nBase = blockIdx.x * 128;
    const int mBase = blockIdx.y * 128;
    const int b     = mBase >> 12;
    const int hwB   = mBase & 4095;
    const int lane  = tid & 31, wid = tid >> 5;
    const int wm = wid >> 2, wn = wid & 3;
    const int r_ = lane >> 2, c_ = lane & 3;

    const float* htbase = inp + (size_t)(b * N_ + i) * C_ * HW_;

    const int krow = tid >> 5;
    const int grp  = tid & 31;
    const int hwA  = hwB + grp * 4;
    const int wchL = tid >> 1;
    const int wf   = (tid & 1) * 4;
    const float* wbase = wo + (size_t)(nBase + wchL) * 512 + 256;  // right half of w_o

    float4 aR[2], wR[2];

    float acc[4][4][4];
#pragma unroll
    for (int mt = 0; mt < 4; mt++)
#pragma unroll
        for (int nt = 0; nt < 4; nt++)
#pragma unroll
            for (int q = 0; q < 4; q++) acc[mt][nt][q] = 0.f;

    const int NK = 256 / 16;

#pragma unroll
    for (int j = 0; j < 2; j++) {
        int kg = krow + j * 8;
        aR[j] = *(const float4*)(g_rh + (size_t)((b << 8) + kg) * HW_ + hwA);
        wR[j] = *(const float4*)(wbase + wf + j * 8);
    }
#pragma unroll
    for (int j = 0; j < 2; j++) {
        float* d = &As[0][(krow + j * 8) * SAS + grp * 4];
        d[0] = tf32r(aR[j].x); d[1] = tf32r(aR[j].y); d[2] = tf32r(aR[j].z); d[3] = tf32r(aR[j].w);
        int kb0 = wf + j * 8;
        Ws[0][(kb0 + 0) * SAS + wchL] = tf32r(wR[j].x);
        Ws[0][(kb0 + 1) * SAS + wchL] = tf32r(wR[j].y);
        Ws[0][(kb0 + 2) * SAS + wchL] = tf32r(wR[j].z);
        Ws[0][(kb0 + 3) * SAS + wchL] = tf32r(wR[j].w);
    }
    __syncthreads();

    for (int t = 0; t < NK; t++) {
        const int buf = t & 1;
        if (t + 1 < NK) {
            int kb = (t + 1) * 16;
#pragma unroll
            for (int j = 0; j < 2; j++) {
                int kg = kb + krow + j * 8;
                aR[j] = *(const float4*)(g_rh + (size_t)((b << 8) + kg) * HW_ + hwA);
                wR[j] = *(const float4*)(wbase + kb + wf + j * 8);
            }
        }
#pragma unroll
        for (int kk = 0; kk < 2; kk++) {
            unsigned af[4][4], bf[4][2];
#pragma unroll
            for (int mt = 0; mt < 4; mt++) {
                const float* p = &As[buf][(kk * 8 + c_) * SAS + wm * 64 + mt * 16 + r_];
                af[mt][0] = __float_as_uint(p[0]);
                af[mt][1] = __float_as_uint(p[8]);
                af[mt][2] = __float_as_uint(p[4 * SAS]);
                af[mt][3] = __float_as_uint(p[4 * SAS + 8]);
            }
#pragma unroll
            for (int nt = 0; nt < 4; nt++) {
                const float* p = &Ws[buf][(kk * 8 + c_) * SAS + wn * 32 + nt * 8 + r_];
                bf[nt][0] = __float_as_uint(p[0]);
                bf[nt][1] = __float_as_uint(p[4 * SAS]);
            }
#pragma unroll
            for (int mt = 0; mt < 4; mt++)
#pragma unroll
                for (int nt = 0; nt < 4; nt++)
                    mma_tf32(acc[mt][nt], af[mt], bf[nt]);
        }
        if (t + 1 < NK) {
            const int nb = buf ^ 1;
#pragma unroll
            for (int j = 0; j < 2; j++) {
                float* d = &As[nb][(krow + j * 8) * SAS + grp * 4];
                d[0] = tf32r(aR[j].x); d[1] = tf32r(aR[j].y); d[2] = tf32r(aR[j].z); d[3] = tf32r(aR[j].w);
                int kb0 = wf + j * 8;
                Ws[nb][(kb0 + 0) * SAS + wchL] = tf32r(wR[j].x);
                Ws[nb][(kb0 + 1) * SAS + wchL] = tf32r(wR[j].y);
                Ws[nb][(kb0 + 2) * SAS + wchL] = tf32r(wR[j].z);
                Ws[nb][(kb0 + 3) * SAS + wchL] = tf32r(wR[j].w);
            }
            __syncthreads();
        }
    }

    const float gm = gamma[0];
#pragma unroll
    for (int mt = 0; mt < 4; mt++)
#pragma unroll
        for (int nt = 0; nt < 4; nt++) {
            int px0 = hwB + wm * 64 + mt * 16 + r_;
            int ch0 = nBase + wn * 32 + nt * 8 + c_ * 2;
#pragma unroll
            for (int q = 0; q < 4; q++) {
                int o  = ch0 + (q & 1);
                int hw = px0 + ((q >> 1) * 8);
                size_t idx = (size_t)((b << 8) + o) * HW_ + hw;
                float opre = acc[mt][nt][q] + g_opart[idx];
                float u  = g_u[idx];
                float ht = htbase[(size_t)o * HW_ + hw];
                float hn = ht * (1.f - u) + tanhf(opre) * u;
                out[((size_t)(b * N_ + i) * C_ + o) * HW_ + hw] = hn * gm + ht;
            }
        }
}

// ---------------- launch ----------------------------------------------------
extern "C" void kernel_launch(void* const* d_in, const int* in_sizes, int n_in,
                              void* d_out, int out_size) {
    const float* inp   = (const float*)d_in[0];
    const float* wgt_w = (const float*)d_in[1];
    const float* w_r   = (const float*)d_in[2];
    const float* b_r   = (const float*)d_in[3];
    const float* w_u   = (const float*)d_in[4];
    const float* b_u   = (const float*)d_in[5];
    const float* w_o   = (const float*)d_in[6];
    const float* b_o   = (const float*)d_in[7];
    const float* gamma = (const float*)d_in[8];
    float* out = (float*)d_out;

    prep_kernel<<<(768 * 512 + 255) / 256, 256>>>(w_u, w_r, w_o, b_u, b_r, b_o);
    sumproj_kernel<<<M_ / 256, 256>>>(inp, wgt_w);

    for (int i = 0; i < N_; i++) {
        mt_kernel<<<(B_ * C_ * HW_) / 256, 256>>>(inp, i);
        gemm1_kernel<<<dim3(6, 256), 256>>>(inp, i);
        gemm2_kernel<<<dim3(2, 256), 256>>>(inp, w_o, gamma, out, i);
    }
}

// round 4
// speedup vs baseline: 1.9889x; 1.0015x over previous
#include <cuda_runtime.h>
#include <math.h>

#define B_ 8
#define N_ 5
#define C_ 256
#define HW_ 4096
#define M_ 32768   // B*HW
#define SAS 136    // smem row stride (floats): (8*k + r) mod 32 distinct -> conflict-free frags

// ---------------- scratch (static device globals; no runtime allocation) ----
__device__ float g_sum  [B_*C_*HW_];
__device__ float g_proj [B_*N_*4*HW_];
__device__ float g_mt   [B_*C_*HW_];
__device__ float g_u    [B_*C_*HW_];
__device__ float g_rh   [B_*C_*HW_];
__device__ float g_opart[B_*C_*HW_];
__device__ float g_Wcat [768*512];
__device__ float g_bcat [768];

__device__ __forceinline__ float tf32r(float x) {
    float r; asm("cvt.rna.tf32.f32 %0, %1;" : "=f"(r) : "f"(x)); return r;
}
__device__ __forceinline__ void mma_tf32(float* d, const unsigned* a, const unsigned* b) {
    asm volatile("mma.sync.aligned.m16n8k8.row.col.f32.tf32.tf32.f32 "
        "{%0,%1,%2,%3},{%4,%5,%6,%7},{%8,%9},{%0,%1,%2,%3};"
        : "+f"(d[0]), "+f"(d[1]), "+f"(d[2]), "+f"(d[3])
        : "r"(a[0]), "r"(a[1]), "r"(a[2]), "r"(a[3]), "r"(b[0]), "r"(b[1]));
}

// ---------------- prep: build concatenated weight matrix ---------------------
__global__ void prep_kernel(const float* __restrict__ wu, const float* __restrict__ wr,
                            const float* __restrict__ wo, const float* __restrict__ bu,
                            const float* __restrict__ br, const float* __restrict__ bo) {
    int idx = blockIdx.x * 256 + threadIdx.x;
    if (idx < 768 * 512) {
        int o = idx >> 9, k = idx & 511;
        float v;
        if (o < 256)       v = wu[o * 512 + k];
        else if (o < 512)  v = wr[(o - 256) * 512 + k];
        else               v = (k < 256) ? wo[(o - 512) * 512 + k] : 0.f;
        g_Wcat[idx] = v;
    }
    if (idx < 768) {
        g_bcat[idx] = (idx < 256) ? bu[idx] : (idx < 512 ? br[idx - 256] : bo[idx - 512]);
    }
}

// ---------------- sum over frames + 20 gate projections per pixel ------------
__global__ void sumproj_kernel(const float* __restrict__ inp, const float* __restrict__ wgt_w) {
    __shared__ float wsm[4 * 256];
    int tid = threadIdx.x;
    for (int t = tid; t < 1024; t += 256) wsm[t] = wgt_w[t];
    __syncthreads();

    int m  = blockIdx.x * 256 + tid;
    int b  = m >> 12;
    int hw = m & 4095;

    float pj[N_][4];
#pragma unroll
    for (int j = 0; j < N_; j++)
#pragma unroll
        for (int p = 0; p < 4; p++) pj[j][p] = 0.f;

    const float* base = inp + (size_t)b * N_ * C_ * HW_ + hw;
    for (int c = 0; c < C_; c++) {
        float w0 = wsm[c], w1 = wsm[256 + c], w2 = wsm[512 + c], w3 = wsm[768 + c];
        float s = 0.f;
#pragma unroll
        for (int j = 0; j < N_; j++) {
            float v = base[(j * C_ + c) * HW_];
            s += v;
            pj[j][0] += v * w0; pj[j][1] += v * w1;
            pj[j][2] += v * w2; pj[j][3] += v * w3;
        }
        g_sum[((b << 8) + c) * HW_ + hw] = s;
    }
#pragma unroll
    for (int j = 0; j < N_; j++)
#pragma unroll
        for (int p = 0; p < 4; p++)
            g_proj[(((b * N_ + j) << 2) + p) * HW_ + hw] = pj[j][p];
}

// ---------------- m_t = sigmoid(wgt[c%4]) * (sum_all - h_t) ------------------
__global__ void mt_kernel(const float* __restrict__ inp, int i) {
    int idx = blockIdx.x * 256 + threadIdx.x;
    int hw = idx & 4095;
    int c  = (idx >> 12) & 255;
    int b  = idx >> 20;
    int p  = c & 3;
    int jp = (p < i) ? p : p + 1;
    float a0 = g_proj[(((b * N_ + i)  << 2) + p) * HW_ + hw];
    float a1 = g_proj[(((b * N_ + jp) << 2) + p) * HW_ + hw];
    float gate = 1.f / (1.f + expf(-(a0 - a1)));
    float ht = inp[(((size_t)(b * N_ + i) << 8) + c) * HW_ + hw];
    g_mt[idx] = gate * (g_sum[idx] - ht);
}

// ---------------- GEMM1 (tf32 tensor): [u;r;opart] = Wcat @ [m_t; h_t] -------
// out tile: 128 pixels (M) x 128 chans (N), K=512, BK=16 double-buffered.
// 8 warps: 2(m) x 4(n); warp tile 64x32; 4x4 m16n8k8 fragments.
__global__ __launch_bounds__(256, 2)
void gemm1_kernel(const float* __restrict__ inp, int i) {
    __shared__ float As[2][16 * SAS];
    __shared__ float Ws[2][16 * SAS];
    const int tid   = threadIdx.x;
    const int nBase = blockIdx.x * 128;
    const int mBase = blockIdx.y * 128;
    const int b     = mBase >> 12;
    const int hwB   = mBase & 4095;
    const int lane  = tid & 31, wid = tid >> 5;
    const int wm = wid >> 2, wn = wid & 3;
    const int r_ = lane >> 2, c_ = lane & 3;

    const float* htbase = inp + (size_t)(b * N_ + i) * C_ * HW_;

    // staging: A (16k x 128px): thread loads rows krow, krow+8, float4 at grp*4
    const int krow = tid >> 5;
    const int grp  = tid & 31;
    const int hwA  = hwB + grp * 4;
    // staging: W: thread owns chan (tid>>1), half f
    const int wchL = tid >> 1;
    const int wf   = (tid & 1) * 4;
    const float* wbase = g_Wcat + (size_t)(nBase + wchL) * 512;

    float4 aR[2], wR[2];

    float acc[4][4][4];
#pragma unroll
    for (int mt = 0; mt < 4; mt++)
#pragma unroll
        for (int nt = 0; nt < 4; nt++)
#pragma unroll
            for (int q = 0; q < 4; q++) acc[mt][nt][q] = 0.f;

    const int NK = 512 / 16;

    // prologue
#pragma unroll
    for (int j = 0; j < 2; j++) {
        int kg = krow + j * 8;
        const float* ap = (kg < 256)
            ? (g_mt + (size_t)((b << 8) + kg) * HW_ + hwA)
            : (htbase + (size_t)(kg - 256) * HW_ + hwA);
        aR[j] = *(const float4*)ap;
        wR[j] = *(const float4*)(wbase + wf + j * 8);
    }
#pragma unroll
    for (int j = 0; j < 2; j++) {
        float* d = &As[0][(krow + j * 8) * SAS + grp * 4];
        d[0] = tf32r(aR[j].x); d[1] = tf32r(aR[j].y); d[2] = tf32r(aR[j].z); d[3] = tf32r(aR[j].w);
        int kb0 = wf + j * 8;
        Ws[0][(kb0 + 0) * SAS + wchL] = tf32r(wR[j].x);
        Ws[0][(kb0 + 1) * SAS + wchL] = tf32r(wR[j].y);
        Ws[0][(kb0 + 2) * SAS + wchL] = tf32r(wR[j].z);
        Ws[0][(kb0 + 3) * SAS + wchL] = tf32r(wR[j].w);
    }
    __syncthreads();

    for (int t = 0; t < NK; t++) {
        const int buf = t & 1;
        if (t + 1 < NK) {
            int kb = (t + 1) * 16;
#pragma unroll
            for (int j = 0; j < 2; j++) {
                int kg = kb + krow + j * 8;
                const float* ap = (kg < 256)
                    ? (g_mt + (size_t)((b << 8) + kg) * HW_ + hwA)
                    : (htbase + (size_t)(kg - 256) * HW_ + hwA);
                aR[j] = *(const float4*)ap;
                wR[j] = *(const float4*)(wbase + kb + wf + j * 8);
            }
        }
#pragma unroll
        for (int kk = 0; kk < 2; kk++) {
            unsigned af[4][4], bf[4][2];
#pragma unroll
            for (int mt = 0; mt < 4; mt++) {
                const float* p = &As[buf][(kk * 8 + c_) * SAS + wm * 64 + mt * 16 + r_];
                af[mt][0] = __float_as_uint(p[0]);
                af[mt][1] = __float_as_uint(p[8]);
                af[mt][2] = __float_as_uint(p[4 * SAS]);
                af[mt][3] = __float_as_uint(p[4 * SAS + 8]);
            }
#pragma unroll
            for (int nt = 0; nt < 4; nt++) {
                const float* p = &Ws[buf][(kk * 8 + c_) * SAS + wn * 32 + nt * 8 + r_];
                bf[nt][0] = __float_as_uint(p[0]);
                bf[nt][1] = __float_as_uint(p[4 * SAS]);
            }
#pragma unroll
            for (int mt = 0; mt < 4; mt++)
#pragma unroll
                for (int nt = 0; nt < 4; nt++)
                    mma_tf32(acc[mt][nt], af[mt], bf[nt]);
        }
        if (t + 1 < NK) {
            const int nb = buf ^ 1;
#pragma unroll
            for (int j = 0; j < 2; j++) {
                float* d = &As[nb][(krow + j * 8) * SAS + grp * 4];
                d[0] = tf32r(aR[j].x); d[1] = tf32r(aR[j].y); d[2] = tf32r(aR[j].z); d[3] = tf32r(aR[j].w);
                int kb0 = wf + j * 8;
                Ws[nb][(kb0 + 0) * SAS + wchL] = tf32r(wR[j].x);
                Ws[nb][(kb0 + 1) * SAS + wchL] = tf32r(wR[j].y);
                Ws[nb][(kb0 + 2) * SAS + wchL] = tf32r(wR[j].z);
                Ws[nb][(kb0 + 3) * SAS + wchL] = tf32r(wR[j].w);
            }
            __syncthreads();
        }
    }

    // epilogue: fragment (q): pixel = px0 + (q>>1)*8, chan = ch0 + (q&1)
    const int seg = nBase >> 8;  // 0=u, 1=r, 2=opart
#pragma unroll
    for (int mt = 0; mt < 4; mt++)
#pragma unroll
        for (int nt = 0; nt < 4; nt++) {
            int px0 = hwB + wm * 64 + mt * 16 + r_;
            int ch0 = nBase + wn * 32 + nt * 8 + c_ * 2;
#pragma unroll
            for (int q = 0; q < 4; q++) {
                int o  = ch0 + (q & 1);
                int hw = px0 + ((q >> 1) * 8);
                float v = acc[mt][nt][q] + g_bcat[o];
                if (seg == 0) {
                    g_u[(size_t)((b << 8) + o) * HW_ + hw] = 1.f / (1.f + expf(-v));
                } else if (seg == 1) {
                    int c = o - 256;
                    float ht = htbase[(size_t)c * HW_ + hw];
                    g_rh[(size_t)((b << 8) + c) * HW_ + hw] = ht / (1.f + expf(-v));
                } else {
                    g_opart[(size_t)((b << 8) + o - 512) * HW_ + hw] = v;
                }
            }
        }
}

// ---------------- GEMM2 (tf32 tensor): o_pre = opart + W_o_right @ rh --------
__global__ __launch_bounds__(256, 2)
void gemm2_kernel(const float* __restrict__ inp, const float* __restrict__ wo,
                  const float* __restrict__ gamma, float* __restrict__ out, int i) {
    __shared__ float As[2][16 * SAS];
    __shared__ float Ws[2][16 * SAS];
    const int tid   = threadIdx.x;
    const int nBase = blockIdx.x * 128;
    const int mBase = blockIdx.y * 128;
    const int b     = mBase >> 12;
    const int hwB   = mBase & 4095;
    const int lane  = tid & 31, wid = tid >> 5;
    const int wm = wid >> 2, wn = wid & 3;
    const int r_ = lane >> 2, c_ = lane & 3;

    const float* htbase = inp + (size_t)(b * N_ + i) * C_ * HW_;

    const int krow = tid >> 5;
    const int grp  = tid & 31;
    const int hwA  = hwB + grp * 4;
    const int wchL = tid >> 1;
    const int wf   = (tid & 1) * 4;
    const float* wbase = wo + (size_t)(nBase + wchL) * 512 + 256;  // right half of w_o

    float4 aR[2], wR[2];

    float acc[4][4][4];
#pragma unroll
    for (int mt = 0; mt < 4; mt++)
#pragma unroll
        for (int nt = 0; nt < 4; nt++)
#pragma unroll
            for (int q = 0; q < 4; q++) acc[mt][nt][q] = 0.f;

    const int NK = 256 / 16;

#pragma unroll
    for (int j = 0; j < 2; j++) {
        int kg = krow + j * 8;
        aR[j] = *(const float4*)(g_rh + (size_t)((b << 8) + kg) * HW_ + hwA);
        wR[j] = *(const float4*)(wbase + wf + j * 8);
    }
#pragma unroll
    for (int j = 0; j < 2; j++) {
        float* d = &As[0][(krow + j * 8) * SAS + grp * 4];
        d[0] = tf32r(aR[j].x); d[1] = tf32r(aR[j].y); d[2] = tf32r(aR[j].z); d[3] = tf32r(aR[j].w);
        int kb0 = wf + j * 8;
        Ws[0][(kb0 + 0) * SAS + wchL] = tf32r(wR[j].x);
        Ws[0][(kb0 + 1) * SAS + wchL] = tf32r(wR[j].y);
        Ws[0][(kb0 + 2) * SAS + wchL] = tf32r(wR[j].z);
        Ws[0][(kb0 + 3) * SAS + wchL] = tf32r(wR[j].w);
    }
    __syncthreads();

    for (int t = 0; t < NK; t++) {
        const int buf = t & 1;
        if (t + 1 < NK) {
            int kb = (t + 1) * 16;
#pragma unroll
            for (int j = 0; j < 2; j++) {
                int kg = kb + krow + j * 8;
                aR[j] = *(const float4*)(g_rh + (size_t)((b << 8) + kg) * HW_ + hwA);
                wR[j] = *(const float4*)(wbase + kb + wf + j * 8);
            }
        }
#pragma unroll
        for (int kk = 0; kk < 2; kk++) {
            unsigned af[4][4], bf[4][2];
#pragma unroll
            for (int mt = 0; mt < 4; mt++) {
                const float* p = &As[buf][(kk * 8 + c_) * SAS + wm * 64 + mt * 16 + r_];
                af[mt][0] = __float_as_uint(p[0]);
                af[mt][1] = __float_as_uint(p[8]);
                af[mt][2] = __float_as_uint(p[4 * SAS]);
                af[mt][3] = __float_as_uint(p[4 * SAS + 8]);
            }
#pragma unroll
            for (int nt = 0; nt < 4; nt++) {
                const float* p = &Ws[buf][(kk * 8 + c_) * SAS + wn * 32 + nt * 8 + r_];
                bf[nt][0] = __float_as_uint(p[0]);
                bf[nt][1] = __float_as_uint(p[4 * SAS]);
            }
#pragma unroll
            for (int mt = 0; mt < 4; mt++)
#pragma unroll
                for (int nt = 0; nt < 4; nt++)
                    mma_tf32(acc[mt][nt], af[mt], bf[nt]);
        }
        if (t + 1 < NK) {
            const int nb = buf ^ 1;
#pragma unroll
            for (int j = 0; j < 2; j++) {
                float* d = &As[nb][(krow + j * 8) * SAS + grp * 4];
                d[0] = tf32r(aR[j].x); d[1] = tf32r(aR[j].y); d[2] = tf32r(aR[j].z); d[3] = tf32r(aR[j].w);
                int kb0 = wf + j * 8;
                Ws[nb][(kb0 + 0) * SAS + wchL] = tf32r(wR[j].x);
                Ws[nb][(kb0 + 1) * SAS + wchL] = tf32r(wR[j].y);
                Ws[nb][(kb0 + 2) * SAS + wchL] = tf32r(wR[j].z);
                Ws[nb][(kb0 + 3) * SAS + wchL] = tf32r(wR[j].w);
            }
            __syncthreads();
        }
    }

    const float gm = gamma[0];
#pragma unroll
    for (int mt = 0; mt < 4; mt++)
#pragma unroll
        for (int nt = 0; nt < 4; nt++) {
            int px0 = hwB + wm * 64 + mt * 16 + r_;
            int ch0 = nBase + wn * 32 + nt * 8 + c_ * 2;
#pragma unroll
            for (int q = 0; q < 4; q++) {
                int o  = ch0 + (q & 1);
                int hw = px0 + ((q >> 1) * 8);
                size_t idx = (size_t)((b << 8) + o) * HW_ + hw;
                float opre = acc[mt][nt][q] + g_opart[idx];
                float u  = g_u[idx];
                float ht = htbase[(size_t)o * HW_ + hw];
                float hn = ht * (1.f - u) + tanhf(opre) * u;
                out[((size_t)(b * N_ + i) * C_ + o) * HW_ + hw] = hn * gm + ht;
            }
        }
}

// ---------------- launch ----------------------------------------------------
extern "C" void kernel_launch(void* const* d_in, const int* in_sizes, int n_in,
                              void* d_out, int out_size) {
    const float* inp   = (const float*)d_in[0];
    const float* wgt_w = (const float*)d_in[1];
    const float* w_r   = (const float*)d_in[2];
    const float* b_r   = (const float*)d_in[3];
    const float* w_u   = (const float*)d_in[4];
    const float* b_u   = (const float*)d_in[5];
    const float* w_o   = (const float*)d_in[6];
    const float* b_o   = (const float*)d_in[7];
    const float* gamma = (const float*)d_in[8];
    float* out = (float*)d_out;

    prep_kernel<<<(768 * 512 + 255) / 256, 256>>>(w_u, w_r, w_o, b_u, b_r, b_o);
    sumproj_kernel<<<M_ / 256, 256>>>(inp, wgt_w);

    for (int i = 0; i < N_; i++) {
        mt_kernel<<<(B_ * C_ * HW_) / 256, 256>>>(inp, i);
        gemm1_kernel<<<dim3(6, 256), 256>>>(inp, i);
        gemm2_kernel<<<dim3(2, 256), 256>>>(inp, w_o, gamma, out, i);
    }
}

// round 5
// speedup vs baseline: 3.2883x; 1.6533x over previous
#include <cuda_runtime.h>
#include <cuda_bf16.h>
#include <math.h>

#define B_ 8
#define N_ 5
#define C_ 256
#define HW_ 4096
#define M_ 32768

// ---------------- scratch ----------------------------------------------------
__device__ float          g_sum  [B_*C_*HW_];
__device__ float          g_proj [B_*N_*4*HW_];
__device__ __nv_bfloat16  g_mtb  [N_*B_*C_*HW_];   // [i][b][c][hw]
__device__ __nv_bfloat16  g_htb  [B_*N_*C_*HW_];   // [b][i][c][hw]
__device__ __nv_bfloat16  g_rhb  [N_*B_*C_*HW_];   // [i][b][c][hw]
__device__ float          g_u    [N_*B_*C_*HW_];
__device__ float          g_opart[N_*B_*C_*HW_];
__device__ __nv_bfloat16  g_Wcatb[768*512];
__device__ __nv_bfloat16  g_Wo2  [256*256];
__device__ float          g_bcat [768];

// ---------------- asm helpers ------------------------------------------------
__device__ __forceinline__ void ldsmx4(unsigned &r0, unsigned &r1, unsigned &r2, unsigned &r3, unsigned a) {
    asm volatile("ldmatrix.sync.aligned.m8n8.x4.shared.b16 {%0,%1,%2,%3},[%4];"
        : "=r"(r0), "=r"(r1), "=r"(r2), "=r"(r3) : "r"(a));
}
__device__ __forceinline__ void ldsmx4t(unsigned &r0, unsigned &r1, unsigned &r2, unsigned &r3, unsigned a) {
    asm volatile("ldmatrix.sync.aligned.m8n8.x4.trans.shared.b16 {%0,%1,%2,%3},[%4];"
        : "=r"(r0), "=r"(r1), "=r"(r2), "=r"(r3) : "r"(a));
}
__device__ __forceinline__ void mma_bf16(float* d, const unsigned* a, unsigned b0, unsigned b1) {
    asm volatile("mma.sync.aligned.m16n8k16.row.col.f32.bf16.bf16.f32 "
        "{%0,%1,%2,%3},{%4,%5,%6,%7},{%8,%9},{%0,%1,%2,%3};"
        : "+f"(d[0]), "+f"(d[1]), "+f"(d[2]), "+f"(d[3])
        : "r"(a[0]), "r"(a[1]), "r"(a[2]), "r"(a[3]), "r"(b0), "r"(b1));
}
#define CPA16(dst, src) asm volatile("cp.async.cg.shared.global [%0],[%1],16;" :: "r"(dst), "l"(src))
#define CPCOMMIT()      asm volatile("cp.async.commit_group;")
#define CPWAIT1()       asm volatile("cp.async.wait_group 1;")
#define CPWAIT0()       asm volatile("cp.async.wait_group 0;")

// ---------------- prep: weights -> bf16 --------------------------------------
__global__ void prep_kernel(const float* __restrict__ wu, const float* __restrict__ wr,
                            const float* __restrict__ wo, const float* __restrict__ bu,
                            const float* __restrict__ br, const float* __restrict__ bo) {
    int idx = blockIdx.x * 256 + threadIdx.x;
    if (idx < 768 * 512) {
        int o = idx >> 9, k = idx & 511;
        float v;
        if (o < 256)       v = wu[o * 512 + k];
        else if (o < 512)  v = wr[(o - 256) * 512 + k];
        else               v = (k < 256) ? wo[(o - 512) * 512 + k] : 0.f;
        g_Wcatb[idx] = __float2bfloat16(v);
    }
    if (idx < 256 * 256) {
        int o = idx >> 8, k = idx & 255;
        g_Wo2[idx] = __float2bfloat16(wo[o * 512 + 256 + k]);
    }
    if (idx < 768)
        g_bcat[idx] = (idx < 256) ? bu[idx] : (idx < 512 ? br[idx - 256] : bo[idx - 512]);
}

// ---------------- sum over frames + 20 gate projections ----------------------
__global__ void sumproj_kernel(const float* __restrict__ inp, const float* __restrict__ wgt_w) {
    __shared__ float wsm[4 * 256];
    int tid = threadIdx.x;
    for (int t = tid; t < 1024; t += 256) wsm[t] = wgt_w[t];
    __syncthreads();
    int m  = blockIdx.x * 256 + tid;
    int b  = m >> 12;
    int hw = m & 4095;
    float pj[N_][4];
#pragma unroll
    for (int j = 0; j < N_; j++)
#pragma unroll
        for (int p = 0; p < 4; p++) pj[j][p] = 0.f;
    const float* base = inp + (size_t)b * N_ * C_ * HW_ + hw;
    for (int c = 0; c < C_; c++) {
        float w0 = wsm[c], w1 = wsm[256 + c], w2 = wsm[512 + c], w3 = wsm[768 + c];
        float s = 0.f;
#pragma unroll
        for (int j = 0; j < N_; j++) {
            float v = base[(j * C_ + c) * HW_];
            s += v;
            pj[j][0] += v * w0; pj[j][1] += v * w1;
            pj[j][2] += v * w2; pj[j][3] += v * w3;
        }
        g_sum[((b << 8) + c) * HW_ + hw] = s;
    }
#pragma unroll
    for (int j = 0; j < N_; j++)
#pragma unroll
        for (int p = 0; p < 4; p++)
            g_proj[(((b * N_ + j) << 2) + p) * HW_ + hw] = pj[j][p];
}

// ---------------- m_t(bf16) + ht(bf16), all i --------------------------------
__global__ void mtht_kernel(const float* __restrict__ inp) {
    int idx = blockIdx.x * 256 + threadIdx.x;   // [i][b][c][hw]
    int hw = idx & 4095;
    int c  = (idx >> 12) & 255;
    int b  = (idx >> 20) & 7;
    int i  = idx >> 23;
    int p  = c & 3;
    int jp = (p < i) ? p : p + 1;
    float a0 = g_proj[(((b * N_ + i)  << 2) + p) * HW_ + hw];
    float a1 = g_proj[(((b * N_ + jp) << 2) + p) * HW_ + hw];
    float gate = 1.f / (1.f + expf(-(a0 - a1)));
    size_t iidx = ((size_t)(b * N_ + i) * C_ + c) * HW_ + hw;
    float ht = inp[iidx];
    float sv = g_sum[((b << 8) + c) * HW_ + hw];
    g_mtb[(size_t)idx] = __float2bfloat16(gate * (sv - ht));
    g_htb[iidx] = __float2bfloat16(ht);
}

// ---------------- GEMM1 (bf16): [u;rh;opart] = Wcat @ [m_t; h_t] -------------
// CTA tile 128px x 128ch, KT=32 double-buffered cp.async, ldmatrix, 8 warps.
__global__ __launch_bounds__(256, 2)
void gemm1_kernel(const float* __restrict__ inp) {
    __shared__ __align__(16) unsigned char sX[2][32 * 272];
    __shared__ __align__(16) unsigned char sW[2][128 * 80];
    const int tid  = threadIdx.x;
    const int lane = tid & 31, wid = tid >> 5;
    const int wm = wid >> 2, wn = wid & 3;
    const int r_ = lane >> 2, c_ = lane & 3;
    const int i     = blockIdx.z;
    const int nBase = blockIdx.x * 128;
    const int mBase = blockIdx.y * 128;
    const int b = mBase >> 12, hwB = mBase & 4095;

    unsigned sXu = (unsigned)__cvta_generic_to_shared(&sX[0][0]);
    unsigned sWu = (unsigned)__cvta_generic_to_shared(&sW[0][0]);

    const int kr = tid >> 3, c0 = tid & 7;       // X staging
    const int nrow = tid >> 1, ch = tid & 1;     // W staging

    const __nv_bfloat16* mtB = g_mtb + (size_t)(i * B_ + b) * C_ * HW_ + hwB;
    const __nv_bfloat16* htB = g_htb + (size_t)(b * N_ + i) * C_ * HW_ + hwB;
    const __nv_bfloat16* wB  = g_Wcatb + (size_t)(nBase + nrow) * 512;

    float acc[4][4][4];
#pragma unroll
    for (int mt = 0; mt < 4; mt++)
#pragma unroll
        for (int nt = 0; nt < 4; nt++)
#pragma unroll
            for (int q = 0; q < 4; q++) acc[mt][nt][q] = 0.f;

    const int rowA = (lane & 7) + ((lane >> 4) << 3);
    const int colA = ((lane >> 3) & 1) << 3;
    const unsigned aAddr0 = sXu + rowA * 272 + (wm * 64 + colA) * 2;
    const int nOffB = (((lane >> 4) & 1) << 3) + (lane & 7);
    const int kOffB = ((lane >> 3) & 1) << 3;
    const unsigned bAddr0 = sWu + (wn * 32 + nOffB) * 80 + kOffB * 2;

    const int NK = 16;   // K = 512
#pragma unroll 1
    for (int t = -1; t < NK; t++) {
        if (t + 1 < NK) {
            int tt = t + 1, buf = tt & 1, kb = tt * 32;
            const __nv_bfloat16* asrc = (kb < 256)
                ? (mtB + (size_t)(kb + kr) * HW_)
                : (htB + (size_t)(kb - 256 + kr) * HW_);
            unsigned xd = sXu + buf * 8704 + kr * 272;
            CPA16(xd + c0 * 16,       asrc + c0 * 8);
            CPA16(xd + (c0 + 8) * 16, asrc + (c0 + 8) * 8);
            const __nv_bfloat16* wsrc = wB + kb;
            unsigned wd = sWu + buf * 10240 + nrow * 80;
            CPA16(wd + ch * 16,       wsrc + ch * 8);
            CPA16(wd + (ch + 2) * 16, wsrc + (ch + 2) * 8);
            CPCOMMIT();
        }
        if (t < 0) continue;
        if (t + 1 < NK) { CPWAIT1(); } else { CPWAIT0(); }
        __syncthreads();
        const int buf = t & 1;
        const unsigned aB = aAddr0 + buf * 8704;
        const unsigned bB = bAddr0 + buf * 10240;
#pragma unroll
        for (int kk = 0; kk < 2; kk++) {
            unsigned af[4][4], bfm[2][4];
#pragma unroll
            for (int mt = 0; mt < 4; mt++)
                ldsmx4t(af[mt][0], af[mt][1], af[mt][2], af[mt][3],
                        aB + kk * (16 * 272) + mt * 32);
#pragma unroll
            for (int np = 0; np < 2; np++)
                ldsmx4(bfm[np][0], bfm[np][1], bfm[np][2], bfm[np][3],
                       bB + kk * 32 + np * (16 * 80));
#pragma unroll
            for (int mt = 0; mt < 4; mt++)
#pragma unroll
                for (int nt = 0; nt < 4; nt++)
                    mma_bf16(acc[mt][nt], af[mt],
                             bfm[nt >> 1][(nt & 1) * 2], bfm[nt >> 1][(nt & 1) * 2 + 1]);
        }
        __syncthreads();
    }

    const int seg = nBase >> 8;   // 0=u, 1=rh, 2=opart
    const float* htf = inp + (size_t)(b * N_ + i) * C_ * HW_;
    const size_t obase = (size_t)(i * B_ + b) * C_;
#pragma unroll
    for (int mt = 0; mt < 4; mt++)
#pragma unroll
        for (int nt = 0; nt < 4; nt++) {
            int px0 = hwB + wm * 64 + mt * 16 + r_;
            int ch0 = nBase + wn * 32 + nt * 8 + c_ * 2;
#pragma unroll
            for (int q = 0; q < 4; q++) {
                int o  = ch0 + (q & 1);
                int hw = px0 + ((q >> 1) << 3);
                float v = acc[mt][nt][q] + g_bcat[o];
                if (seg == 0) {
                    g_u[(obase + o) * HW_ + hw] = 1.f / (1.f + expf(-v));
                } else if (seg == 1) {
                    int c = o - 256;
                    float ht = htf[(size_t)c * HW_ + hw];
                    g_rhb[(obase + c) * HW_ + hw] = __float2bfloat16(ht / (1.f + expf(-v)));
                } else {
                    g_opart[(obase + o - 512) * HW_ + hw] = v;
                }
            }
        }
}

// ---------------- GEMM2 (bf16): o_pre = opart + Wo2 @ rh; final combine ------
__global__ __launch_bounds__(256, 2)
void gemm2_kernel(const float* __restrict__ inp, const float* __restrict__ gamma,
                  float* __restrict__ out) {
    __shared__ __align__(16) unsigned char sX[2][32 * 272];
    __shared__ __align__(16) unsigned char sW[2][128 * 80];
    const int tid  = threadIdx.x;
    const int lane = tid & 31, wid = tid >> 5;
    const int wm = wid >> 2, wn = wid & 3;
    const int r_ = lane >> 2, c_ = lane & 3;
    const int i     = blockIdx.z;
    const int nBase = blockIdx.x * 128;
    const int mBase = blockIdx.y * 128;
    const int b = mBase >> 12, hwB = mBase & 4095;

    unsigned sXu = (unsigned)__cvta_generic_to_shared(&sX[0][0]);
    unsigned sWu = (unsigned)__cvta_generic_to_shared(&sW[0][0]);

    const int kr = tid >> 3, c0 = tid & 7;
    const int nrow = tid >> 1, ch = tid & 1;

    const __nv_bfloat16* rhB = g_rhb + (size_t)(i * B_ + b) * C_ * HW_ + hwB;
    const __nv_bfloat16* wB  = g_Wo2 + (size_t)(nBase + nrow) * 256;

    float acc[4][4][4];
#pragma unroll
    for (int mt = 0; mt < 4; mt++)
#pragma unroll
        for (int nt = 0; nt < 4; nt++)
#pragma unroll
            for (int q = 0; q < 4; q++) acc[mt][nt][q] = 0.f;

    const int rowA = (lane & 7) + ((lane >> 4) << 3);
    const int colA = ((lane >> 3) & 1) << 3;
    const unsigned aAddr0 = sXu + rowA * 272 + (wm * 64 + colA) * 2;
    const int nOffB = (((lane >> 4) & 1) << 3) + (lane & 7);
    const int kOffB = ((lane >> 3) & 1) << 3;
    const unsigned bAddr0 = sWu + (wn * 32 + nOffB) * 80 + kOffB * 2;

    const int NK = 8;   // K = 256
#pragma unroll 1
    for (int t = -1; t < NK; t++) {
        if (t + 1 < NK) {
            int tt = t + 1, buf = tt & 1, kb = tt * 32;
            const __nv_bfloat16* asrc = rhB + (size_t)(kb + kr) * HW_;
            unsigned xd = sXu + buf * 8704 + kr * 272;
            CPA16(xd + c0 * 16,       asrc + c0 * 8);
            CPA16(xd + (c0 + 8) * 16, asrc + (c0 + 8) * 8);
            const __nv_bfloat16* wsrc = wB + kb;
            unsigned wd = sWu + buf * 10240 + nrow * 80;
            CPA16(wd + ch * 16,       wsrc + ch * 8);
            CPA16(wd + (ch + 2) * 16, wsrc + (ch + 2) * 8);
            CPCOMMIT();
        }
        if (t < 0) continue;
        if (t + 1 < NK) { CPWAIT1(); } else { CPWAIT0(); }
        __syncthreads();
        const int buf = t & 1;
        const unsigned aB = aAddr0 + buf * 8704;
        const unsigned bB = bAddr0 + buf * 10240;
#pragma unroll
        for (int kk = 0; kk < 2; kk++) {
            unsigned af[4][4], bfm[2][4];
#pragma unroll
            for (int mt = 0; mt < 4; mt++)
                ldsmx4t(af[mt][0], af[mt][1], af[mt][2], af[mt][3],
                        aB + kk * (16 * 272) + mt * 32);
#pragma unroll
            for (int np = 0; np < 2; np++)
                ldsmx4(bfm[np][0], bfm[np][1], bfm[np][2], bfm[np][3],
                       bB + kk * 32 + np * (16 * 80));
#pragma unroll
            for (int mt = 0; mt < 4; mt++)
#pragma unroll
                for (int nt = 0; nt < 4; nt++)
                    mma_bf16(acc[mt][nt], af[mt],
                             bfm[nt >> 1][(nt & 1) * 2], bfm[nt >> 1][(nt & 1) * 2 + 1]);
        }
        __syncthreads();
    }

    const float gm = gamma[0];
    const float* htf = inp + (size_t)(b * N_ + i) * C_ * HW_;
    const size_t obase = (size_t)(i * B_ + b) * C_;
#pragma unroll
    for (int mt = 0; mt < 4; mt++)
#pragma unroll
        for (int nt = 0; nt < 4; nt++) {
            int px0 = hwB + wm * 64 + mt * 16 + r_;
            int ch0 = nBase + wn * 32 + nt * 8 + c_ * 2;
#pragma unroll
            for (int q = 0; q < 4; q++) {
                int o  = ch0 + (q & 1);
                int hw = px0 + ((q >> 1) << 3);
                size_t idx = (obase + o) * HW_ + hw;
                float opre = acc[mt][nt][q] + g_opart[idx];
                float u  = g_u[idx];
                float ht = htf[(size_t)o * HW_ + hw];
                float hn = ht * (1.f - u) + tanhf(opre) * u;
                out[((size_t)(b * N_ + i) * C_ + o) * HW_ + hw] = hn * gm + ht;
            }
        }
}

// ---------------- launch ----------------------------------------------------
extern "C" void kernel_launch(void* const* d_in, const int* in_sizes, int n_in,
                              void* d_out, int out_size) {
    const float* inp   = (const float*)d_in[0];
    const float* wgt_w = (const float*)d_in[1];
    const float* w_r   = (const float*)d_in[2];
    const float* b_r   = (const float*)d_in[3];
    const float* w_u   = (const float*)d_in[4];
    const float* b_u   = (const float*)d_in[5];
    const float* w_o   = (const float*)d_in[6];
    const float* b_o   = (const float*)d_in[7];
    const float* gamma = (const float*)d_in[8];
    float* out = (float*)d_out;

    prep_kernel<<<1536, 256>>>(w_u, w_r, w_o, b_u, b_r, b_o);
    sumproj_kernel<<<M_ / 256, 256>>>(inp, wgt_w);
    mtht_kernel<<<(N_ * B_ * C_ * HW_) / 256, 256>>>(inp);
    gemm1_kernel<<<dim3(6, 256, 5), 256>>>(inp);
    gemm2_kernel<<<dim3(2, 256, 5), 256>>>(inp, gamma, out);
}

// round 6
// speedup vs baseline: 3.3853x; 1.0295x over previous
#include <cuda_runtime.h>
#include <cuda_bf16.h>
#include <math.h>

#define B_ 8
#define N_ 5
#define C_ 256
#define HW_ 4096
#define M_ 32768
#define SMEMSZ (4*8704 + 4*10240)   // 4-stage X + W

// ---------------- scratch ----------------------------------------------------
__device__ float          g_sum  [B_*C_*HW_];
__device__ float          g_proj [B_*N_*4*HW_];
__device__ __nv_bfloat16  g_mtb  [N_*B_*C_*HW_];   // [i][b][c][hw]
__device__ __nv_bfloat16  g_htb  [B_*N_*C_*HW_];   // [b][i][c][hw]
__device__ __nv_bfloat16  g_rhb  [N_*B_*C_*HW_];   // [i][b][c][hw]
__device__ float          g_u    [N_*B_*C_*HW_];
__device__ float          g_opart[N_*B_*C_*HW_];
__device__ __nv_bfloat16  g_Wcatb[768*512];
__device__ __nv_bfloat16  g_Wo2  [256*256];
__device__ float          g_bcat [768];

// ---------------- asm helpers ------------------------------------------------
__device__ __forceinline__ void ldsmx4(unsigned &r0, unsigned &r1, unsigned &r2, unsigned &r3, unsigned a) {
    asm volatile("ldmatrix.sync.aligned.m8n8.x4.shared.b16 {%0,%1,%2,%3},[%4];"
        : "=r"(r0), "=r"(r1), "=r"(r2), "=r"(r3) : "r"(a));
}
__device__ __forceinline__ void ldsmx4t(unsigned &r0, unsigned &r1, unsigned &r2, unsigned &r3, unsigned a) {
    asm volatile("ldmatrix.sync.aligned.m8n8.x4.trans.shared.b16 {%0,%1,%2,%3},[%4];"
        : "=r"(r0), "=r"(r1), "=r"(r2), "=r"(r3) : "r"(a));
}
__device__ __forceinline__ void mma_bf16(float* d, const unsigned* a, unsigned b0, unsigned b1) {
    asm volatile("mma.sync.aligned.m16n8k16.row.col.f32.bf16.bf16.f32 "
        "{%0,%1,%2,%3},{%4,%5,%6,%7},{%8,%9},{%0,%1,%2,%3};"
        : "+f"(d[0]), "+f"(d[1]), "+f"(d[2]), "+f"(d[3])
        : "r"(a[0]), "r"(a[1]), "r"(a[2]), "r"(a[3]), "r"(b0), "r"(b1));
}
#define CPA16(dst, src) asm volatile("cp.async.cg.shared.global [%0],[%1],16;" :: "r"(dst), "l"(src))
#define CPCOMMIT()      asm volatile("cp.async.commit_group;" ::: "memory")
#define CPWAIT2()       asm volatile("cp.async.wait_group 2;" ::: "memory")

// ---------------- prep: weights -> bf16 --------------------------------------
__global__ void prep_kernel(const float* __restrict__ wu, const float* __restrict__ wr,
                            const float* __restrict__ wo, const float* __restrict__ bu,
                            const float* __restrict__ br, const float* __restrict__ bo) {
    int idx = blockIdx.x * 256 + threadIdx.x;
    if (idx < 768 * 512) {
        int o = idx >> 9, k = idx & 511;
        float v;
        if (o < 256)       v = wu[o * 512 + k];
        else if (o < 512)  v = wr[(o - 256) * 512 + k];
        else               v = (k < 256) ? wo[(o - 512) * 512 + k] : 0.f;
        g_Wcatb[idx] = __float2bfloat16(v);
    }
    if (idx < 256 * 256) {
        int o = idx >> 8, k = idx & 255;
        g_Wo2[idx] = __float2bfloat16(wo[o * 512 + 256 + k]);
    }
    if (idx < 768)
        g_bcat[idx] = (idx < 256) ? bu[idx] : (idx < 512 ? br[idx - 256] : bo[idx - 512]);
}

// ---------------- sum over frames + 20 gate projections ----------------------
__global__ void sumproj_kernel(const float* __restrict__ inp, const float* __restrict__ wgt_w) {
    __shared__ float wsm[4 * 256];
    int tid = threadIdx.x;
    for (int t = tid; t < 1024; t += 256) wsm[t] = wgt_w[t];
    __syncthreads();
    int m  = blockIdx.x * 256 + tid;
    int b  = m >> 12;
    int hw = m & 4095;
    float pj[N_][4];
#pragma unroll
    for (int j = 0; j < N_; j++)
#pragma unroll
        for (int p = 0; p < 4; p++) pj[j][p] = 0.f;
    const float* base = inp + (size_t)b * N_ * C_ * HW_ + hw;
    for (int c = 0; c < C_; c++) {
        float w0 = wsm[c], w1 = wsm[256 + c], w2 = wsm[512 + c], w3 = wsm[768 + c];
        float s = 0.f;
#pragma unroll
        for (int j = 0; j < N_; j++) {
            float v = base[(j * C_ + c) * HW_];
            s += v;
            pj[j][0] += v * w0; pj[j][1] += v * w1;
            pj[j][2] += v * w2; pj[j][3] += v * w3;
        }
        g_sum[((b << 8) + c) * HW_ + hw] = s;
    }
#pragma unroll
    for (int j = 0; j < N_; j++)
#pragma unroll
        for (int p = 0; p < 4; p++)
            g_proj[(((b * N_ + j) << 2) + p) * HW_ + hw] = pj[j][p];
}

// ---------------- m_t(bf16) + ht(bf16), all i --------------------------------
__global__ void mtht_kernel(const float* __restrict__ inp) {
    int idx = blockIdx.x * 256 + threadIdx.x;   // [i][b][c][hw]
    int hw = idx & 4095;
    int c  = (idx >> 12) & 255;
    int b  = (idx >> 20) & 7;
    int i  = idx >> 23;
    int p  = c & 3;
    int jp = (p < i) ? p : p + 1;
    float a0 = g_proj[(((b * N_ + i)  << 2) + p) * HW_ + hw];
    float a1 = g_proj[(((b * N_ + jp) << 2) + p) * HW_ + hw];
    float gate = 1.f / (1.f + expf(-(a0 - a1)));
    size_t iidx = ((size_t)(b * N_ + i) * C_ + c) * HW_ + hw;
    float ht = inp[iidx];
    float sv = g_sum[((b << 8) + c) * HW_ + hw];
    g_mtb[(size_t)idx] = __float2bfloat16(gate * (sv - ht));
    g_htb[iidx] = __float2bfloat16(ht);
}

// ---------------- GEMM1 (bf16): [u;rh;opart] = Wcat @ [m_t; h_t] -------------
// CTA tile 128px x 128ch, 4-stage cp.async ring, 1 syncthreads/tile.
__global__ __launch_bounds__(256, 2)
void gemm1_kernel(const float* __restrict__ inp) {
    extern __shared__ __align__(16) unsigned char smem_dyn[];
    const int tid  = threadIdx.x;
    const int lane = tid & 31, wid = tid >> 5;
    const int wm = wid >> 2, wn = wid & 3;
    const int r_ = lane >> 2, c_ = lane & 3;
    const int i     = blockIdx.z;
    const int nBase = blockIdx.x * 128;
    const int mBase = blockIdx.y * 128;
    const int b = mBase >> 12, hwB = mBase & 4095;

    unsigned sXu = (unsigned)__cvta_generic_to_shared(smem_dyn);
    unsigned sWu = sXu + 4 * 8704;

    const int kr = tid >> 3, c0 = tid & 7;       // X staging
    const int nrow = tid >> 1, ch = tid & 1;     // W staging

    const __nv_bfloat16* mtB = g_mtb + (size_t)(i * B_ + b) * C_ * HW_ + hwB;
    const __nv_bfloat16* htB = g_htb + (size_t)(b * N_ + i) * C_ * HW_ + hwB;
    const __nv_bfloat16* wB  = g_Wcatb + (size_t)(nBase + nrow) * 512;

    auto issue = [&](int tt) {
        int st = tt & 3, kb = tt * 32;
        const __nv_bfloat16* asrc = (kb < 256)
            ? (mtB + (size_t)(kb + kr) * HW_)
            : (htB + (size_t)(kb - 256 + kr) * HW_);
        unsigned xd = sXu + st * 8704 + kr * 272;
        CPA16(xd + c0 * 16,       asrc + c0 * 8);
        CPA16(xd + (c0 + 8) * 16, asrc + (c0 + 8) * 8);
        const __nv_bfloat16* wsrc = wB + kb;
        unsigned wd = sWu + st * 10240 + nrow * 80;
        CPA16(wd + ch * 16,       wsrc + ch * 8);
        CPA16(wd + (ch + 2) * 16, wsrc + (ch + 2) * 8);
    };

    float acc[4][4][4];
#pragma unroll
    for (int mt = 0; mt < 4; mt++)
#pragma unroll
        for (int nt = 0; nt < 4; nt++)
#pragma unroll
            for (int q = 0; q < 4; q++) acc[mt][nt][q] = 0.f;

    const int rowA = (lane & 7) + ((lane >> 4) << 3);
    const int colA = ((lane >> 3) & 1) << 3;
    const unsigned aAddr0 = sXu + rowA * 272 + (wm * 64 + colA) * 2;
    const int nOffB = (((lane >> 4) & 1) << 3) + (lane & 7);
    const int kOffB = ((lane >> 3) & 1) << 3;
    const unsigned bAddr0 = sWu + (wn * 32 + nOffB) * 80 + kOffB * 2;

    const int NK = 16;   // K = 512
#pragma unroll
    for (int tt = 0; tt < 3; tt++) { issue(tt); CPCOMMIT(); }
#pragma unroll 1
    for (int t = 0; t < NK; t++) {
        CPWAIT2();
        __syncthreads();
        if (t + 3 < NK) issue(t + 3);
        CPCOMMIT();
        const int st = t & 3;
        const unsigned aB = aAddr0 + st * 8704;
        const unsigned bB = bAddr0 + st * 10240;
#pragma unroll
        for (int kk = 0; kk < 2; kk++) {
            unsigned af[4][4], bfm[2][4];
#pragma unroll
            for (int mt = 0; mt < 4; mt++)
                ldsmx4t(af[mt][0], af[mt][1], af[mt][2], af[mt][3],
                        aB + kk * (16 * 272) + mt * 32);
#pragma unroll
            for (int np = 0; np < 2; np++)
                ldsmx4(bfm[np][0], bfm[np][1], bfm[np][2], bfm[np][3],
                       bB + kk * 32 + np * (16 * 80));
#pragma unroll
            for (int mt = 0; mt < 4; mt++)
#pragma unroll
                for (int nt = 0; nt < 4; nt++)
                    mma_bf16(acc[mt][nt], af[mt],
                             bfm[nt >> 1][(nt & 1) * 2], bfm[nt >> 1][(nt & 1) * 2 + 1]);
        }
    }

    const int seg = nBase >> 8;   // 0=u, 1=rh, 2=opart
    const float* htf = inp + (size_t)(b * N_ + i) * C_ * HW_;
    const size_t obase = (size_t)(i * B_ + b) * C_;
#pragma unroll
    for (int mt = 0; mt < 4; mt++)
#pragma unroll
        for (int nt = 0; nt < 4; nt++) {
            int px0 = hwB + wm * 64 + mt * 16 + r_;
            int ch0 = nBase + wn * 32 + nt * 8 + c_ * 2;
#pragma unroll
            for (int q = 0; q < 4; q++) {
                int o  = ch0 + (q & 1);
                int hw = px0 + ((q >> 1) << 3);
                float v = acc[mt][nt][q] + g_bcat[o];
                if (seg == 0) {
                    g_u[(obase + o) * HW_ + hw] = 1.f / (1.f + expf(-v));
                } else if (seg == 1) {
                    int c = o - 256;
                    float ht = htf[(size_t)c * HW_ + hw];
                    g_rhb[(obase + c) * HW_ + hw] = __float2bfloat16(ht / (1.f + expf(-v)));
                } else {
                    g_opart[(obase + o - 512) * HW_ + hw] = v;
                }
            }
        }
}

// ---------------- GEMM2 (bf16): o_pre = opart + Wo2 @ rh; final combine ------
__global__ __launch_bounds__(256, 2)
void gemm2_kernel(const float* __restrict__ inp, const float* __restrict__ gamma,
                  float* __restrict__ out) {
    extern __shared__ __align__(16) unsigned char smem_dyn[];
    const int tid  = threadIdx.x;
    const int lane = tid & 31, wid = tid >> 5;
    const int wm = wid >> 2, wn = wid & 3;
    const int r_ = lane >> 2, c_ = lane & 3;
    const int i     = blockIdx.z;
    const int nBase = blockIdx.x * 128;
    const int mBase = blockIdx.y * 128;
    const int b = mBase >> 12, hwB = mBase & 4095;

    unsigned sXu = (unsigned)__cvta_generic_to_shared(smem_dyn);
    unsigned sWu = sXu + 4 * 8704;

    const int kr = tid >> 3, c0 = tid & 7;
    const int nrow = tid >> 1, ch = tid & 1;

    const __nv_bfloat16* rhB = g_rhb + (size_t)(i * B_ + b) * C_ * HW_ + hwB;
    const __nv_bfloat16* wB  = g_Wo2 + (size_t)(nBase + nrow) * 256;

    auto issue = [&](int tt) {
        int st = tt & 3, kb = tt * 32;
        const __nv_bfloat16* asrc = rhB + (size_t)(kb + kr) * HW_;
        unsigned xd = sXu + st * 8704 + kr * 272;
        CPA16(xd + c0 * 16,       asrc + c0 * 8);
        CPA16(xd + (c0 + 8) * 16, asrc + (c0 + 8) * 8);
        const __nv_bfloat16* wsrc = wB + kb;
        unsigned wd = sWu + st * 10240 + nrow * 80;
        CPA16(wd + ch * 16,       wsrc + ch * 8);
        CPA16(wd + (ch + 2) * 16, wsrc + (ch + 2) * 8);
    };

    float acc[4][4][4];
#pragma unroll
    for (int mt = 0; mt < 4; mt++)
#pragma unroll
        for (int nt = 0; nt < 4; nt++)
#pragma unroll
            for (int q = 0; q < 4; q++) acc[mt][nt][q] = 0.f;

    const int rowA = (lane & 7) + ((lane >> 4) << 3);
    const int colA = ((lane >> 3) & 1) << 3;
    const unsigned aAddr0 = sXu + rowA * 272 + (wm * 64 + colA) * 2;
    const int nOffB = (((lane >> 4) & 1) << 3) + (lane & 7);
    const int kOffB = ((lane >> 3) & 1) << 3;
    const unsigned bAddr0 = sWu + (wn * 32 + nOffB) * 80 + kOffB * 2;

    const int NK = 8;   // K = 256
#pragma unroll
    for (int tt = 0; tt < 3; tt++) { issue(tt); CPCOMMIT(); }
#pragma unroll 1
    for (int t = 0; t < NK; t++) {
        CPWAIT2();
        __syncthreads();
        if (t + 3 < NK) issue(t + 3);
        CPCOMMIT();
        const int st = t & 3;
        const unsigned aB = aAddr0 + st * 8704;
        const unsigned bB = bAddr0 + st * 10240;
#pragma unroll
        for (int kk = 0; kk < 2; kk++) {
            unsigned af[4][4], bfm[2][4];
#pragma unroll
            for (int mt = 0; mt < 4; mt++)
                ldsmx4t(af[mt][0], af[mt][1], af[mt][2], af[mt][3],
                        aB + kk * (16 * 272) + mt * 32);
#pragma unroll
            for (int np = 0; np < 2; np++)
                ldsmx4(bfm[np][0], bfm[np][1], bfm[np][2], bfm[np][3],
                       bB + kk * 32 + np * (16 * 80));
#pragma unroll
            for (int mt = 0; mt < 4; mt++)
#pragma unroll
                for (int nt = 0; nt < 4; nt++)
                    mma_bf16(acc[mt][nt], af[mt],
                             bfm[nt >> 1][(nt & 1) * 2], bfm[nt >> 1][(nt & 1) * 2 + 1]);
        }
    }

    const float gm = gamma[0];
    const float* htf = inp + (size_t)(b * N_ + i) * C_ * HW_;
    const size_t obase = (size_t)(i * B_ + b) * C_;
#pragma unroll
    for (int mt = 0; mt < 4; mt++)
#pragma unroll
        for (int nt = 0; nt < 4; nt++) {
            int px0 = hwB + wm * 64 + mt * 16 + r_;
            int ch0 = nBase + wn * 32 + nt * 8 + c_ * 2;
#pragma unroll
            for (int q = 0; q < 4; q++) {
                int o  = ch0 + (q & 1);
                int hw = px0 + ((q >> 1) << 3);
                size_t idx = (obase + o) * HW_ + hw;
                float opre = acc[mt][nt][q] + g_opart[idx];
                float u  = g_u[idx];
                float ht = htf[(size_t)o * HW_ + hw];
                float hn = ht * (1.f - u) + tanhf(opre) * u;
                out[((size_t)(b * N_ + i) * C_ + o) * HW_ + hw] = hn * gm + ht;
            }
        }
}

// ---------------- launch ----------------------------------------------------
extern "C" void kernel_launch(void* const* d_in, const int* in_sizes, int n_in,
                              void* d_out, int out_size) {
    const float* inp   = (const float*)d_in[0];
    const float* wgt_w = (const float*)d_in[1];
    const float* w_r   = (const float*)d_in[2];
    const float* b_r   = (const float*)d_in[3];
    const float* w_u   = (const float*)d_in[4];
    const float* b_u   = (const float*)d_in[5];
    const float* w_o   = (const float*)d_in[6];
    const float* b_o   = (const float*)d_in[7];
    const float* gamma = (const float*)d_in[8];
    float* out = (float*)d_out;

    cudaFuncSetAttribute(gemm1_kernel, cudaFuncAttributeMaxDynamicSharedMemorySize, SMEMSZ);
    cudaFuncSetAttribute(gemm2_kernel, cudaFuncAttributeMaxDynamicSharedMemorySize, SMEMSZ);

    prep_kernel<<<1536, 256>>>(w_u, w_r, w_o, b_u, b_r, b_o);
    sumproj_kernel<<<M_ / 256, 256>>>(inp, wgt_w);
    mtht_kernel<<<(N_ * B_ * C_ * HW_) / 256, 256>>>(inp);
    gemm1_kernel<<<dim3(6, 256, 5), 256, SMEMSZ>>>(inp);
    gemm2_kernel<<<dim3(2, 256, 5), 256, SMEMSZ>>>(inp, gamma, out);
}